// round 5
// baseline (speedup 1.0000x reference)
#include <cuda_runtime.h>
#include <math.h>
#include <stdint.h>

#define Bsz 2
#define Ssz 2048
#define Dsz 1024
#define Hsz 16
#define Msz (Bsz * Ssz)            // 4096 rows
#define CHUNK (4096ull * 1024ull)  // 4M floats

// QKV(6) + OB(2) + TB(2) chunks (BSS, no alloc)
__device__ __align__(1024) float g_scratch[10ull * CHUNK];

// ---------------------------------------------------------------------------
// helpers
// ---------------------------------------------------------------------------
__device__ __forceinline__ uint32_t cvta_smem(const void* p) {
    uint32_t a;
    asm("{ .reg .u64 t; cvta.to.shared.u64 t, %1; cvt.u32.u64 %0, t; }"
        : "=r"(a) : "l"(p));
    return a;
}
__device__ __forceinline__ void cp16(uint32_t dst, const void* src) {
    asm volatile("cp.async.cg.shared.global [%0], [%1], 16;" :: "r"(dst), "l"(src));
}
__device__ __forceinline__ void cp_commit() { asm volatile("cp.async.commit_group;"); }
template <int N>
__device__ __forceinline__ void cp_wait() { asm volatile("cp.async.wait_group %0;" :: "n"(N)); }

__device__ __forceinline__ float rna_tf32(float v) {
    uint32_t b;
    asm("cvt.rna.tf32.f32 %0, %1;" : "=r"(b) : "f"(v));
    return __uint_as_float(b);
}
__device__ __forceinline__ uint32_t rna_bits(float v) {
    uint32_t b;
    asm("cvt.rna.tf32.f32 %0, %1;" : "=r"(b) : "f"(v));
    return b;
}

// mma.sync m16n8k8 tf32: D += A(16x8, row) * B(8x8, col)
__device__ __forceinline__ void mma8(float c[4], const uint32_t a[4],
                                     uint32_t b0, uint32_t b1) {
    asm volatile(
        "mma.sync.aligned.m16n8k8.row.col.f32.tf32.tf32.f32 "
        "{%0,%1,%2,%3}, {%4,%5,%6,%7}, {%8,%9}, {%0,%1,%2,%3};"
        : "+f"(c[0]), "+f"(c[1]), "+f"(c[2]), "+f"(c[3])
        : "r"(a[0]), "r"(a[1]), "r"(a[2]), "r"(a[3]), "r"(b0), "r"(b1));
}

struct Ptrs6 { const float* p[6]; };

// ---------------------------------------------------------------------------
// tf32 mma.sync GEMM, CTA tile 128x256, BK=32, 8 warps (warp tile 64x64).
// All operand fragments rounded to tf32 (RN) in-register.
// VAR 0 (QKV):  A[M,1024] raw; B = 6 weights [1024,1024]; epilogue rounds.
// VAR 1 (WO):   A[M,2048] block-diag (col block = n0>>10); B = 2 weights.
// VAR 2 (FINAL):A = rna(T1 - lam*T2) from TB[M,2048]; B = Wp.
// ---------------------------------------------------------------------------
#define ALD 36
#define BLD 264
#define ASZ (128 * ALD)           // 4608 floats
#define BSZ_ (32 * BLD)           // 8448 floats

template <int VAR>
__global__ __launch_bounds__(256, 1)
void gemm_mma(const float* __restrict__ A, Ptrs6 Bp, Ptrs6 biasP,
              float* __restrict__ C, int N, int lda, int ldc,
              const float* __restrict__ lambda_param,
              const unsigned* __restrict__ layer_idx_bits)
{
    constexpr int AS_TOT = (VAR == 2) ? 2 * ASZ : ASZ;
    extern __shared__ float sm[];
    float* As = sm;                       // [2][AS_TOT]
    float* Bs = sm + 2 * AS_TOT;          // [2][BSZ_]
    const uint32_t sbA = cvta_smem(As);
    const uint32_t sbB = cvta_smem(Bs);

    const int tid = threadIdx.x;
    const int wid = tid >> 5, lane = tid & 31;
    const int g = lane >> 2, t = lane & 3;
    const int wm = wid >> 2, wn = wid & 3;       // 2 x 4 warp grid
    const int m0 = blockIdx.y * 128, n0 = blockIdx.x * 256;
    const int j = n0 >> 10;
    const int aoff = (VAR == 1) ? (j << 10) : 0;

    float lam = 0.f;
    if (VAR == 2) {
        unsigned bits = *layer_idx_bits;
        float lf = (bits < 10000u) ? (float)bits : __uint_as_float(bits);
        float e = __expf(-0.3f * fmaxf(lf - 1.0f, 0.0f));
        lam = fminf(fmaxf((0.8f - 0.6f * e) * lambda_param[0], 0.1f), 0.9f);
    }

    const float* Bj = Bp.p[j] + (n0 & 1023);

    float c[4][8][4] = {};

    auto loadA = [&](int buf, int kt) {
#pragma unroll
        for (int i = 0; i < 4; i++) {
            int idx = tid + i * 256;
            int row = idx >> 3, c4 = (idx & 7) << 2;
            const float* src = A + (size_t)(m0 + row) * lda + aoff + kt * 32 + c4;
            cp16(sbA + (uint32_t)(buf * AS_TOT + row * ALD + c4) * 4u, src);
            if (VAR == 2)
                cp16(sbA + (uint32_t)(buf * AS_TOT + ASZ + row * ALD + c4) * 4u, src + 1024);
        }
    };
    auto loadB = [&](int buf, int kt) {
#pragma unroll
        for (int i = 0; i < 8; i++) {
            int idx = tid + i * 256;
            int row = idx >> 6, c4 = (idx & 63) << 2;
            cp16(sbB + (uint32_t)(buf * BSZ_ + row * BLD + c4) * 4u,
                 Bj + (size_t)(kt * 32 + row) * 1024 + c4);
        }
    };

    const int T = 1024 / 32;
    loadA(0, 0); loadB(0, 0); cp_commit();

    for (int kt = 0; kt < T; kt++) {
        const int buf = kt & 1;
        if (kt + 1 < T) { loadA(buf ^ 1, kt + 1); loadB(buf ^ 1, kt + 1); cp_commit(); cp_wait<1>(); }
        else cp_wait<0>();
        __syncthreads();

        const float* Abf = As + buf * AS_TOT;
        const float* Bbf = Bs + buf * BSZ_;
#pragma unroll
        for (int ks = 0; ks < 4; ks++) {
            uint32_t a[4][4];
#pragma unroll
            for (int mf = 0; mf < 4; mf++) {
                int rb = wm * 64 + mf * 16;
#pragma unroll
                for (int q = 0; q < 4; q++) {
                    int r = rb + ((q & 1) ? g + 8 : g);
                    int kk = ks * 8 + t + ((q >> 1) ? 4 : 0);
                    float v = Abf[r * ALD + kk];
                    if (VAR == 2) {
                        float v2 = Abf[ASZ + r * ALD + kk];
                        v = fmaf(-lam, v2, v);
                    }
                    a[mf][q] = rna_bits(v);
                }
            }
#pragma unroll
            for (int nf = 0; nf < 8; nf++) {
                uint32_t b0 = rna_bits(Bbf[(ks * 8 + t) * BLD + wn * 64 + nf * 8 + g]);
                uint32_t b1 = rna_bits(Bbf[(ks * 8 + t + 4) * BLD + wn * 64 + nf * 8 + g]);
#pragma unroll
                for (int mf = 0; mf < 4; mf++)
                    mma8(c[mf][nf], a[mf], b0, b1);
            }
        }
        __syncthreads();
    }

    const float* bb = biasP.p[j] + (n0 & 1023);
#pragma unroll
    for (int mf = 0; mf < 4; mf++) {
        int r0 = m0 + wm * 64 + mf * 16 + g;
#pragma unroll
        for (int nf = 0; nf < 8; nf++) {
            int cl = wn * 64 + nf * 8 + 2 * t;
            float bv0 = bb[cl], bv1 = bb[cl + 1];
            float v00 = c[mf][nf][0] + bv0, v01 = c[mf][nf][1] + bv1;
            float v10 = c[mf][nf][2] + bv0, v11 = c[mf][nf][3] + bv1;
            if (VAR == 0) {
                v00 = rna_tf32(v00); v01 = rna_tf32(v01);
                v10 = rna_tf32(v10); v11 = rna_tf32(v11);
            }
            float2 lo = { v00, v01 }, hi = { v10, v11 };
            *(float2*)(C + (size_t)r0 * ldc + n0 + cl) = lo;
            *(float2*)(C + (size_t)(r0 + 8) * ldc + n0 + cl) = hi;
        }
    }
}

// ---------------------------------------------------------------------------
// Flash attention, tf32 mma.sync, both branches via blockIdx.z.
// QKV: [M, 6144] fused (Q1 K1 V1 Q2 K2 V2 blocks). O: [M, 2048].
// CTA: 8 warps, 256 q-rows (32/warp). KV tile 64, double-buffered.
// ---------------------------------------------------------------------------
#define KLD 68
#define VLD 72
#define PLD 68
#define KSZ (64 * KLD)
#define VSZ (64 * VLD)
#define PSZ (256 * PLD)
#define ATT_SMEM ((2 * KSZ + 2 * VSZ + PSZ) * 4)   // 141312 B

__global__ __launch_bounds__(256, 1)
void flash_mma(const float* __restrict__ QKV, float* __restrict__ O)
{
    extern __shared__ float sm[];
    float* Ks = sm;
    float* Vs = sm + 2 * KSZ;
    float* Ps = sm + 2 * KSZ + 2 * VSZ;
    const uint32_t sbK = cvta_smem(Ks);
    const uint32_t sbV = cvta_smem(Vs);

    const int tid = threadIdx.x;
    const int w = tid >> 5, lane = tid & 31;
    const int g = lane >> 2, t = lane & 3;
    const int b = blockIdx.y >> 4, h = blockIdx.y & 15, z = blockIdx.z;
    const int q0 = blockIdx.x * 256;
    const size_t ld = 6144;

    const float* Qb = QKV + (size_t)b * Ssz * ld + (size_t)z * 3072 + h * 64;
    const float* Kg = Qb + 1024;
    const float* Vg = Qb + 2048;

    // Q fragments, scaled by 1/8 (exact pow2, stays tf32)
    uint32_t qf[2][8][4];
#pragma unroll
    for (int mf = 0; mf < 2; mf++) {
        const float* r0p = Qb + (size_t)(q0 + w * 32 + mf * 16 + g) * ld;
        const float* r1p = r0p + 8 * ld;
#pragma unroll
        for (int kf = 0; kf < 8; kf++) {
            qf[mf][kf][0] = __float_as_uint(r0p[kf * 8 + t] * 0.125f);
            qf[mf][kf][1] = __float_as_uint(r1p[kf * 8 + t] * 0.125f);
            qf[mf][kf][2] = __float_as_uint(r0p[kf * 8 + t + 4] * 0.125f);
            qf[mf][kf][3] = __float_as_uint(r1p[kf * 8 + t + 4] * 0.125f);
        }
    }

    float o[2][8][4] = {};
    float mm[2][2] = { {-1e30f, -1e30f}, {-1e30f, -1e30f} };
    float ll[2][2] = {};

    auto loadKV = [&](int buf, int tile) {
#pragma unroll
        for (int i = 0; i < 4; i++) {
            int idx = tid + i * 256;
            int row = idx >> 4, c4 = (idx & 15) << 2;
            size_t src = (size_t)(tile * 64 + row) * ld + c4;
            cp16(sbK + (uint32_t)(buf * KSZ + row * KLD + c4) * 4u, Kg + src);
            cp16(sbV + (uint32_t)(buf * VSZ + row * VLD + c4) * 4u, Vg + src);
        }
    };

    const int NT = Ssz / 64;   // 32
    loadKV(0, 0); cp_commit();

    const int pr00 = (w * 32 + g) * PLD;
    const int pr01 = pr00 + 8 * PLD;
    const int pr10 = pr00 + 16 * PLD;
    const int pr11 = pr00 + 24 * PLD;
    uint32_t* Pu = (uint32_t*)Ps;

    for (int tile = 0; tile < NT; tile++) {
        const int buf = tile & 1;
        if (tile + 1 < NT) { loadKV(buf ^ 1, tile + 1); cp_commit(); cp_wait<1>(); }
        else cp_wait<0>();
        __syncthreads();

        const uint32_t* Kb = (const uint32_t*)(Ks + buf * KSZ);
        const uint32_t* Vb = (const uint32_t*)(Vs + buf * VSZ);

        // S = Q * K^T  (32 x 64 per warp)
        float s[2][8][4] = {};
#pragma unroll
        for (int kf = 0; kf < 8; kf++) {
#pragma unroll
            for (int nf = 0; nf < 8; nf++) {
                uint32_t b0 = Kb[(nf * 8 + g) * KLD + kf * 8 + t];
                uint32_t b1 = Kb[(nf * 8 + g) * KLD + kf * 8 + t + 4];
                mma8(s[0][nf], qf[0][kf], b0, b1);
                mma8(s[1][nf], qf[1][kf], b0, b1);
            }
        }

        // online softmax per m-fragment
#pragma unroll
        for (int mf = 0; mf < 2; mf++) {
            float tmax0 = -1e30f, tmax1 = -1e30f;
#pragma unroll
            for (int nf = 0; nf < 8; nf++) {
                tmax0 = fmaxf(tmax0, fmaxf(s[mf][nf][0], s[mf][nf][1]));
                tmax1 = fmaxf(tmax1, fmaxf(s[mf][nf][2], s[mf][nf][3]));
            }
            tmax0 = fmaxf(tmax0, __shfl_xor_sync(0xffffffffu, tmax0, 1));
            tmax0 = fmaxf(tmax0, __shfl_xor_sync(0xffffffffu, tmax0, 2));
            tmax1 = fmaxf(tmax1, __shfl_xor_sync(0xffffffffu, tmax1, 1));
            tmax1 = fmaxf(tmax1, __shfl_xor_sync(0xffffffffu, tmax1, 2));

            float mn0 = fmaxf(mm[mf][0], tmax0), mn1 = fmaxf(mm[mf][1], tmax1);
            float al0 = __expf(mm[mf][0] - mn0), al1 = __expf(mm[mf][1] - mn1);

            const int prow0 = (mf == 0) ? pr00 : pr10;
            const int prow1 = (mf == 0) ? pr01 : pr11;
            float rs0 = 0.f, rs1 = 0.f;
#pragma unroll
            for (int nf = 0; nf < 8; nf++) {
                uint32_t r0 = rna_bits(__expf(s[mf][nf][0] - mn0));
                uint32_t r1 = rna_bits(__expf(s[mf][nf][1] - mn0));
                uint32_t r2 = rna_bits(__expf(s[mf][nf][2] - mn1));
                uint32_t r3 = rna_bits(__expf(s[mf][nf][3] - mn1));
                rs0 += __uint_as_float(r0) + __uint_as_float(r1);
                rs1 += __uint_as_float(r2) + __uint_as_float(r3);
                Pu[prow0 + nf * 8 + 2 * t]     = r0;
                Pu[prow0 + nf * 8 + 2 * t + 1] = r1;
                Pu[prow1 + nf * 8 + 2 * t]     = r2;
                Pu[prow1 + nf * 8 + 2 * t + 1] = r3;
            }
            rs0 += __shfl_xor_sync(0xffffffffu, rs0, 1);
            rs0 += __shfl_xor_sync(0xffffffffu, rs0, 2);
            rs1 += __shfl_xor_sync(0xffffffffu, rs1, 1);
            rs1 += __shfl_xor_sync(0xffffffffu, rs1, 2);
            ll[mf][0] = ll[mf][0] * al0 + rs0;
            ll[mf][1] = ll[mf][1] * al1 + rs1;
            mm[mf][0] = mn0; mm[mf][1] = mn1;
#pragma unroll
            for (int nf = 0; nf < 8; nf++) {
                o[mf][nf][0] *= al0; o[mf][nf][1] *= al0;
                o[mf][nf][2] *= al1; o[mf][nf][3] *= al1;
            }
        }
        __syncwarp();

        // O += P * V
        const uint32_t* Pr = (const uint32_t*)Ps;
#pragma unroll
        for (int kf = 0; kf < 8; kf++) {
            uint32_t a0[4], a1[4];
            a0[0] = Pr[pr00 + kf * 8 + t];     a0[1] = Pr[pr01 + kf * 8 + t];
            a0[2] = Pr[pr00 + kf * 8 + t + 4]; a0[3] = Pr[pr01 + kf * 8 + t + 4];
            a1[0] = Pr[pr10 + kf * 8 + t];     a1[1] = Pr[pr11 + kf * 8 + t];
            a1[2] = Pr[pr10 + kf * 8 + t + 4]; a1[3] = Pr[pr11 + kf * 8 + t + 4];
#pragma unroll
            for (int nf = 0; nf < 8; nf++) {
                uint32_t b0 = Vb[(kf * 8 + t) * VLD + nf * 8 + g];
                uint32_t b1 = Vb[(kf * 8 + t + 4) * VLD + nf * 8 + g];
                mma8(o[0][nf], a0, b0, b1);
                mma8(o[1][nf], a1, b0, b1);
            }
        }
        __syncthreads();
    }

#pragma unroll
    for (int mf = 0; mf < 2; mf++) {
        float inv0 = 1.f / ll[mf][0], inv1 = 1.f / ll[mf][1];
        int row = q0 + w * 32 + mf * 16 + g;
        float* Orow = O + (size_t)(b * Ssz + row) * 2048 + z * 1024 + h * 64;
#pragma unroll
        for (int nf = 0; nf < 8; nf++) {
            int col = nf * 8 + 2 * t;
            float2 lo = { rna_tf32(o[mf][nf][0] * inv0), rna_tf32(o[mf][nf][1] * inv0) };
            float2 hi = { rna_tf32(o[mf][nf][2] * inv1), rna_tf32(o[mf][nf][3] * inv1) };
            *(float2*)(Orow + col) = lo;
            *(float2*)(Orow + 8 * 2048 + col) = hi;
        }
    }
}

// ---------------------------------------------------------------------------
extern "C" void kernel_launch(void* const* d_in, const int* in_sizes, int n_in,
                              void* d_out, int out_size)
{
    const float*    x            = (const float*)d_in[0];
    const unsigned* layer_idx    = (const unsigned*)d_in[1];
    const float*    lambda_param = (const float*)d_in[2];

    const float *Wq1, *bq1, *Wk1, *bk1, *Wv1, *bv1, *Wo1, *bo1;
    const float *Wq2, *bq2, *Wk2, *bk2, *Wv2, *bv2, *Wo2, *bo2;

    bool sig_order = (in_sizes[4] < 100000);
    if (!sig_order) {
        Wq1 = (const float*)d_in[3];  Wk1 = (const float*)d_in[4];
        Wv1 = (const float*)d_in[5];  Wo1 = (const float*)d_in[6];
        bq1 = (const float*)d_in[7];  bk1 = (const float*)d_in[8];
        bv1 = (const float*)d_in[9];  bo1 = (const float*)d_in[10];
        Wq2 = (const float*)d_in[11]; Wk2 = (const float*)d_in[12];
        Wv2 = (const float*)d_in[13]; Wo2 = (const float*)d_in[14];
        bq2 = (const float*)d_in[15]; bk2 = (const float*)d_in[16];
        bv2 = (const float*)d_in[17]; bo2 = (const float*)d_in[18];
    } else {
        Wq1 = (const float*)d_in[3];  bq1 = (const float*)d_in[4];
        Wk1 = (const float*)d_in[5];  bk1 = (const float*)d_in[6];
        Wv1 = (const float*)d_in[7];  bv1 = (const float*)d_in[8];
        Wo1 = (const float*)d_in[9];  bo1 = (const float*)d_in[10];
        Wq2 = (const float*)d_in[11]; bq2 = (const float*)d_in[12];
        Wk2 = (const float*)d_in[13]; bk2 = (const float*)d_in[14];
        Wv2 = (const float*)d_in[15]; bv2 = (const float*)d_in[16];
        Wo2 = (const float*)d_in[17]; bo2 = (const float*)d_in[18];
    }
    const float* Wp = (const float*)d_in[19];
    const float* bp = (const float*)d_in[20];

    float* s = nullptr;
    cudaGetSymbolAddress((void**)&s, g_scratch);
    float* QKV = s;                 // [4096,6144]
    float* OB  = s + 6 * CHUNK;     // [4096,2048]
    float* TB  = s + 8 * CHUNK;     // [4096,2048]

    const int GEMM_SMEM01 = (2 * ASZ + 2 * BSZ_) * 4;   // 104448
    const int GEMM_SMEM2  = (4 * ASZ + 2 * BSZ_) * 4;   // 141312

    cudaFuncSetAttribute(gemm_mma<0>, cudaFuncAttributeMaxDynamicSharedMemorySize, GEMM_SMEM01);
    cudaFuncSetAttribute(gemm_mma<1>, cudaFuncAttributeMaxDynamicSharedMemorySize, GEMM_SMEM01);
    cudaFuncSetAttribute(gemm_mma<2>, cudaFuncAttributeMaxDynamicSharedMemorySize, GEMM_SMEM2);
    cudaFuncSetAttribute(flash_mma,   cudaFuncAttributeMaxDynamicSharedMemorySize, ATT_SMEM);

    // fused QKV projection: [4096,1024] x 6x[1024,1024] -> [4096,6144]
    Ptrs6 wqkv = {{ Wq1, Wk1, Wv1, Wq2, Wk2, Wv2 }};
    Ptrs6 bqkv = {{ bq1, bk1, bv1, bq2, bk2, bv2 }};
    gemm_mma<0><<<dim3(24, 32), 256, GEMM_SMEM01>>>(x, wqkv, bqkv, QKV, 6144, 1024, 6144,
                                                    nullptr, nullptr);

    // attention, both branches
    flash_mma<<<dim3(Ssz / 256, Bsz * Hsz, 2), 256, ATT_SMEM>>>(QKV, OB);

    // fused output projections (block-diagonal A)
    Ptrs6 wwo = {{ Wo1, Wo2, nullptr, nullptr, nullptr, nullptr }};
    Ptrs6 bwo = {{ bo1, bo2, nullptr, nullptr, nullptr, nullptr }};
    gemm_mma<1><<<dim3(8, 32), 256, GEMM_SMEM01>>>(OB, wwo, bwo, TB, 2048, 2048, 2048,
                                                   nullptr, nullptr);

    // final projection with fused diff: (T1 - lam*T2) @ Wp + bp -> d_out
    Ptrs6 wp = {{ Wp, nullptr, nullptr, nullptr, nullptr, nullptr }};
    Ptrs6 bpp = {{ bp, nullptr, nullptr, nullptr, nullptr, nullptr }};
    gemm_mma<2><<<dim3(4, 32), 256, GEMM_SMEM2>>>(TB, wp, bpp, (float*)d_out, 1024, 2048, 1024,
                                                  lambda_param, layer_idx);
}

// round 6
// speedup vs baseline: 1.0240x; 1.0240x over previous
#include <cuda_runtime.h>
#include <math.h>
#include <stdint.h>

#define Bsz 2
#define Ssz 2048
#define Dsz 1024
#define Hsz 16
#define Msz (Bsz * Ssz)            // 4096 rows
#define CHUNK (4096ull * 1024ull)  // 4M floats
#define WCH   (1024ull * 1024ull)  // 1M floats

// XR(1) + WR(9 WCH) + QKV(6) + OB(2) + TB(2)
__device__ __align__(1024) float g_scratch[11ull * CHUNK + 9ull * WCH];

// ---------------------------------------------------------------------------
// helpers
// ---------------------------------------------------------------------------
__device__ __forceinline__ uint32_t cvta_smem(const void* p) {
    uint32_t a;
    asm("{ .reg .u64 t; cvta.to.shared.u64 t, %1; cvt.u32.u64 %0, t; }"
        : "=r"(a) : "l"(p));
    return a;
}
__device__ __forceinline__ void cp16(uint32_t dst, const void* src) {
    asm volatile("cp.async.cg.shared.global [%0], [%1], 16;" :: "r"(dst), "l"(src));
}
__device__ __forceinline__ void cp_commit() { asm volatile("cp.async.commit_group;"); }
template <int N>
__device__ __forceinline__ void cp_wait() { asm volatile("cp.async.wait_group %0;" :: "n"(N)); }

__device__ __forceinline__ float rna_tf32(float v) {
    uint32_t b;
    asm("cvt.rna.tf32.f32 %0, %1;" : "=r"(b) : "f"(v));
    return __uint_as_float(b);
}
__device__ __forceinline__ uint32_t rna_bits(float v) {
    uint32_t b;
    asm("cvt.rna.tf32.f32 %0, %1;" : "=r"(b) : "f"(v));
    return b;
}

// mma.sync m16n8k8 tf32: D += A(16x8, row) * B(8x8, col)
__device__ __forceinline__ void mma8(float c[4], const uint32_t a[4],
                                     uint32_t b0, uint32_t b1) {
    asm volatile(
        "mma.sync.aligned.m16n8k8.row.col.f32.tf32.tf32.f32 "
        "{%0,%1,%2,%3}, {%4,%5,%6,%7}, {%8,%9}, {%0,%1,%2,%3};"
        : "+f"(c[0]), "+f"(c[1]), "+f"(c[2]), "+f"(c[3])
        : "r"(a[0]), "r"(a[1]), "r"(a[2]), "r"(a[3]), "r"(b0), "r"(b1));
}

struct Ptrs6 { const float* p[6]; };
struct Ptrs10 { const float4* p[10]; };

// ---------------------------------------------------------------------------
// prep: RN-round x (1M float4) + 9 weights (256K float4 each) into scratch
// ---------------------------------------------------------------------------
__device__ __forceinline__ float4 rna4(float4 v) {
    v.x = rna_tf32(v.x); v.y = rna_tf32(v.y);
    v.z = rna_tf32(v.z); v.w = rna_tf32(v.w);
    return v;
}

__global__ void prep_round(Ptrs10 src, float4* __restrict__ dst)
{
    const int total = 1048576 + 9 * 262144;   // 3,407,872 float4
    int i = blockIdx.x * blockDim.x + threadIdx.x;
    int st = gridDim.x * blockDim.x;
    for (; i < total; i += st) {
        int which, off;
        if (i < 1048576) { which = 0; off = i; }
        else { which = 1 + ((i - 1048576) >> 18); off = (i - 1048576) & 262143; }
        dst[i] = rna4(src.p[which][off]);
    }
}

// ---------------------------------------------------------------------------
// tf32 mma.sync GEMM, CTA tile 128x256, BK=32, 8 warps (warp tile 64x64).
// 3-stage cp.async pipeline + register fragment double-buffering.
// VAR 0 (QKV):  A=XR rounded; 6 B weights; epilogue rounds.
// VAR 1 (WO):   A=OB rounded, block-diag (col block = n0>>10); 2 B weights.
// VAR 2 (FINAL):A = rna(T1 - lam*T2) from TB[M,2048]; B = Wp rounded.
// ---------------------------------------------------------------------------
#define ALD 36
#define BLD 264
#define ASZ (128 * ALD)           // 4608 floats
#define BSZ_ (32 * BLD)           // 8448 floats

template <int VAR>
__global__ __launch_bounds__(256, 1)
void gemm_mma(const float* __restrict__ A, Ptrs6 Bp, Ptrs6 biasP,
              float* __restrict__ C, int N, int lda, int ldc,
              const float* __restrict__ lambda_param,
              const unsigned* __restrict__ layer_idx_bits)
{
    constexpr int A_ST = (VAR == 2) ? 2 * ASZ : ASZ;   // floats of A per stage
    constexpr int STG = A_ST + BSZ_;                    // floats per stage
    extern __shared__ float sm[];
    const uint32_t sbase = cvta_smem(sm);

    const int tid = threadIdx.x;
    const int wid = tid >> 5, lane = tid & 31;
    const int g = lane >> 2, t = lane & 3;
    const int wm = wid >> 2, wn = wid & 3;       // 2 x 4 warp grid
    const int m0 = blockIdx.y * 128, n0 = blockIdx.x * 256;
    const int j = n0 >> 10;
    const int aoff = (VAR == 1) ? (j << 10) : 0;

    float lam = 0.f;
    if (VAR == 2) {
        unsigned bits = *layer_idx_bits;
        float lf = (bits < 10000u) ? (float)bits : __uint_as_float(bits);
        float e = __expf(-0.3f * fmaxf(lf - 1.0f, 0.0f));
        lam = fminf(fmaxf((0.8f - 0.6f * e) * lambda_param[0], 0.1f), 0.9f);
    }

    const float* Bj = Bp.p[j] + (n0 & 1023);

    float c[4][8][4] = {};

    auto loadTile = [&](int stg, int kt) {
        uint32_t sa = sbase + (uint32_t)(stg * STG) * 4u;
        uint32_t sb = sa + (uint32_t)A_ST * 4u;
#pragma unroll
        for (int i = 0; i < 4; i++) {
            int idx = tid + i * 256;
            int row = idx >> 3, c4 = (idx & 7) << 2;
            const float* src = A + (size_t)(m0 + row) * lda + aoff + kt * 32 + c4;
            cp16(sa + (uint32_t)(row * ALD + c4) * 4u, src);
            if (VAR == 2)
                cp16(sa + (uint32_t)(ASZ + row * ALD + c4) * 4u, src + 1024);
        }
#pragma unroll
        for (int i = 0; i < 8; i++) {
            int idx = tid + i * 256;
            int row = idx >> 6, c4 = (idx & 63) << 2;
            cp16(sb + (uint32_t)(row * BLD + c4) * 4u,
                 Bj + (size_t)(kt * 32 + row) * 1024 + c4);
        }
        cp_commit();
    };

    const int T = 1024 / 32;   // 32 k-tiles
    loadTile(0, 0);
    loadTile(1, 1);

    for (int kt = 0; kt < T; kt++) {
        const int stg = kt % 3;
        if (kt < T - 1) cp_wait<1>(); else cp_wait<0>();
        __syncthreads();
        if (kt + 2 < T) loadTile((kt + 2) % 3, kt + 2);

        const float* Abf = sm + stg * STG;
        const float* Bbf = Abf + A_ST;

        uint32_t aF[2][4][4];
        uint32_t bF[2][2][8];

        auto ldfrag = [&](int ks, int slot) {
#pragma unroll
            for (int mf = 0; mf < 4; mf++) {
                int rb = wm * 64 + mf * 16;
#pragma unroll
                for (int q = 0; q < 4; q++) {
                    int r = rb + ((q & 1) ? g + 8 : g);
                    int kk = ks * 8 + t + ((q >> 1) ? 4 : 0);
                    if (VAR == 2) {
                        float v = fmaf(-lam, Abf[ASZ + r * ALD + kk], Abf[r * ALD + kk]);
                        aF[slot][mf][q] = rna_bits(v);
                    } else {
                        aF[slot][mf][q] = __float_as_uint(Abf[r * ALD + kk]);
                    }
                }
            }
#pragma unroll
            for (int nf = 0; nf < 8; nf++) {
                bF[slot][0][nf] = __float_as_uint(Bbf[(ks * 8 + t) * BLD + wn * 64 + nf * 8 + g]);
                bF[slot][1][nf] = __float_as_uint(Bbf[(ks * 8 + t + 4) * BLD + wn * 64 + nf * 8 + g]);
            }
        };

        ldfrag(0, 0);
#pragma unroll
        for (int ks = 0; ks < 4; ks++) {
            const int cur = ks & 1;
            if (ks < 3) ldfrag(ks + 1, cur ^ 1);
#pragma unroll
            for (int nf = 0; nf < 8; nf++)
#pragma unroll
                for (int mf = 0; mf < 4; mf++)
                    mma8(c[mf][nf], aF[cur][mf], bF[cur][0][nf], bF[cur][1][nf]);
        }
    }

    const float* bb = biasP.p[j] + (n0 & 1023);
#pragma unroll
    for (int mf = 0; mf < 4; mf++) {
        int r0 = m0 + wm * 64 + mf * 16 + g;
#pragma unroll
        for (int nf = 0; nf < 8; nf++) {
            int cl = wn * 64 + nf * 8 + 2 * t;
            float bv0 = bb[cl], bv1 = bb[cl + 1];
            float v00 = c[mf][nf][0] + bv0, v01 = c[mf][nf][1] + bv1;
            float v10 = c[mf][nf][2] + bv0, v11 = c[mf][nf][3] + bv1;
            if (VAR == 0) {
                v00 = rna_tf32(v00); v01 = rna_tf32(v01);
                v10 = rna_tf32(v10); v11 = rna_tf32(v11);
            }
            float2 lo = { v00, v01 }, hi = { v10, v11 };
            *(float2*)(C + (size_t)r0 * ldc + n0 + cl) = lo;
            *(float2*)(C + (size_t)(r0 + 8) * ldc + n0 + cl) = hi;
        }
    }
}

// ---------------------------------------------------------------------------
// Flash attention, tf32 mma.sync, both branches via blockIdx.z. (unchanged)
// QKV: [M, 6144] fused (Q1 K1 V1 Q2 K2 V2 blocks). O: [M, 2048].
// ---------------------------------------------------------------------------
#define KLD 68
#define VLD 72
#define PLD 68
#define KSZ (64 * KLD)
#define VSZ (64 * VLD)
#define PSZ (256 * PLD)
#define ATT_SMEM ((2 * KSZ + 2 * VSZ + PSZ) * 4)   // 141312 B

__global__ __launch_bounds__(256, 1)
void flash_mma(const float* __restrict__ QKV, float* __restrict__ O)
{
    extern __shared__ float sm[];
    float* Ks = sm;
    float* Vs = sm + 2 * KSZ;
    float* Ps = sm + 2 * KSZ + 2 * VSZ;
    const uint32_t sbK = cvta_smem(Ks);
    const uint32_t sbV = cvta_smem(Vs);

    const int tid = threadIdx.x;
    const int w = tid >> 5, lane = tid & 31;
    const int g = lane >> 2, t = lane & 3;
    const int b = blockIdx.y >> 4, h = blockIdx.y & 15, z = blockIdx.z;
    const int q0 = blockIdx.x * 256;
    const size_t ld = 6144;

    const float* Qb = QKV + (size_t)b * Ssz * ld + (size_t)z * 3072 + h * 64;
    const float* Kg = Qb + 1024;
    const float* Vg = Qb + 2048;

    uint32_t qf[2][8][4];
#pragma unroll
    for (int mf = 0; mf < 2; mf++) {
        const float* r0p = Qb + (size_t)(q0 + w * 32 + mf * 16 + g) * ld;
        const float* r1p = r0p + 8 * ld;
#pragma unroll
        for (int kf = 0; kf < 8; kf++) {
            qf[mf][kf][0] = __float_as_uint(r0p[kf * 8 + t] * 0.125f);
            qf[mf][kf][1] = __float_as_uint(r1p[kf * 8 + t] * 0.125f);
            qf[mf][kf][2] = __float_as_uint(r0p[kf * 8 + t + 4] * 0.125f);
            qf[mf][kf][3] = __float_as_uint(r1p[kf * 8 + t + 4] * 0.125f);
        }
    }

    float o[2][8][4] = {};
    float mm[2][2] = { {-1e30f, -1e30f}, {-1e30f, -1e30f} };
    float ll[2][2] = {};

    auto loadKV = [&](int buf, int tile) {
#pragma unroll
        for (int i = 0; i < 4; i++) {
            int idx = tid + i * 256;
            int row = idx >> 4, c4 = (idx & 15) << 2;
            size_t src = (size_t)(tile * 64 + row) * ld + c4;
            cp16(sbK + (uint32_t)(buf * KSZ + row * KLD + c4) * 4u, Kg + src);
            cp16(sbV + (uint32_t)(buf * VSZ + row * VLD + c4) * 4u, Vg + src);
        }
    };

    const int NT = Ssz / 64;   // 32
    loadKV(0, 0); cp_commit();

    const int pr00 = (w * 32 + g) * PLD;
    const int pr01 = pr00 + 8 * PLD;
    const int pr10 = pr00 + 16 * PLD;
    const int pr11 = pr00 + 24 * PLD;
    uint32_t* Pu = (uint32_t*)Ps;

    for (int tile = 0; tile < NT; tile++) {
        const int buf = tile & 1;
        if (tile + 1 < NT) { loadKV(buf ^ 1, tile + 1); cp_commit(); cp_wait<1>(); }
        else cp_wait<0>();
        __syncthreads();

        const uint32_t* Kb = (const uint32_t*)(Ks + buf * KSZ);
        const uint32_t* Vb = (const uint32_t*)(Vs + buf * VSZ);

        float s[2][8][4] = {};
#pragma unroll
        for (int kf = 0; kf < 8; kf++) {
#pragma unroll
            for (int nf = 0; nf < 8; nf++) {
                uint32_t b0 = Kb[(nf * 8 + g) * KLD + kf * 8 + t];
                uint32_t b1 = Kb[(nf * 8 + g) * KLD + kf * 8 + t + 4];
                mma8(s[0][nf], qf[0][kf], b0, b1);
                mma8(s[1][nf], qf[1][kf], b0, b1);
            }
        }

#pragma unroll
        for (int mf = 0; mf < 2; mf++) {
            float tmax0 = -1e30f, tmax1 = -1e30f;
#pragma unroll
            for (int nf = 0; nf < 8; nf++) {
                tmax0 = fmaxf(tmax0, fmaxf(s[mf][nf][0], s[mf][nf][1]));
                tmax1 = fmaxf(tmax1, fmaxf(s[mf][nf][2], s[mf][nf][3]));
            }
            tmax0 = fmaxf(tmax0, __shfl_xor_sync(0xffffffffu, tmax0, 1));
            tmax0 = fmaxf(tmax0, __shfl_xor_sync(0xffffffffu, tmax0, 2));
            tmax1 = fmaxf(tmax1, __shfl_xor_sync(0xffffffffu, tmax1, 1));
            tmax1 = fmaxf(tmax1, __shfl_xor_sync(0xffffffffu, tmax1, 2));

            float mn0 = fmaxf(mm[mf][0], tmax0), mn1 = fmaxf(mm[mf][1], tmax1);
            float al0 = __expf(mm[mf][0] - mn0), al1 = __expf(mm[mf][1] - mn1);

            const int prow0 = (mf == 0) ? pr00 : pr10;
            const int prow1 = (mf == 0) ? pr01 : pr11;
            float rs0 = 0.f, rs1 = 0.f;
#pragma unroll
            for (int nf = 0; nf < 8; nf++) {
                uint32_t r0 = rna_bits(__expf(s[mf][nf][0] - mn0));
                uint32_t r1 = rna_bits(__expf(s[mf][nf][1] - mn0));
                uint32_t r2 = rna_bits(__expf(s[mf][nf][2] - mn1));
                uint32_t r3 = rna_bits(__expf(s[mf][nf][3] - mn1));
                rs0 += __uint_as_float(r0) + __uint_as_float(r1);
                rs1 += __uint_as_float(r2) + __uint_as_float(r3);
                Pu[prow0 + nf * 8 + 2 * t]     = r0;
                Pu[prow0 + nf * 8 + 2 * t + 1] = r1;
                Pu[prow1 + nf * 8 + 2 * t]     = r2;
                Pu[prow1 + nf * 8 + 2 * t + 1] = r3;
            }
            rs0 += __shfl_xor_sync(0xffffffffu, rs0, 1);
            rs0 += __shfl_xor_sync(0xffffffffu, rs0, 2);
            rs1 += __shfl_xor_sync(0xffffffffu, rs1, 1);
            rs1 += __shfl_xor_sync(0xffffffffu, rs1, 2);
            ll[mf][0] = ll[mf][0] * al0 + rs0;
            ll[mf][1] = ll[mf][1] * al1 + rs1;
            mm[mf][0] = mn0; mm[mf][1] = mn1;
#pragma unroll
            for (int nf = 0; nf < 8; nf++) {
                o[mf][nf][0] *= al0; o[mf][nf][1] *= al0;
                o[mf][nf][2] *= al1; o[mf][nf][3] *= al1;
            }
        }
        __syncwarp();

        const uint32_t* Pr = (const uint32_t*)Ps;
#pragma unroll
        for (int kf = 0; kf < 8; kf++) {
            uint32_t a0[4], a1[4];
            a0[0] = Pr[pr00 + kf * 8 + t];     a0[1] = Pr[pr01 + kf * 8 + t];
            a0[2] = Pr[pr00 + kf * 8 + t + 4]; a0[3] = Pr[pr01 + kf * 8 + t + 4];
            a1[0] = Pr[pr10 + kf * 8 + t];     a1[1] = Pr[pr11 + kf * 8 + t];
            a1[2] = Pr[pr10 + kf * 8 + t + 4]; a1[3] = Pr[pr11 + kf * 8 + t + 4];
#pragma unroll
            for (int nf = 0; nf < 8; nf++) {
                uint32_t b0 = Vb[(kf * 8 + t) * VLD + nf * 8 + g];
                uint32_t b1 = Vb[(kf * 8 + t + 4) * VLD + nf * 8 + g];
                mma8(o[0][nf], a0, b0, b1);
                mma8(o[1][nf], a1, b0, b1);
            }
        }
        __syncthreads();
    }

#pragma unroll
    for (int mf = 0; mf < 2; mf++) {
        float inv0 = 1.f / ll[mf][0], inv1 = 1.f / ll[mf][1];
        int row = q0 + w * 32 + mf * 16 + g;
        float* Orow = O + (size_t)(b * Ssz + row) * 2048 + z * 1024 + h * 64;
#pragma unroll
        for (int nf = 0; nf < 8; nf++) {
            int col = nf * 8 + 2 * t;
            float2 lo = { rna_tf32(o[mf][nf][0] * inv0), rna_tf32(o[mf][nf][1] * inv0) };
            float2 hi = { rna_tf32(o[mf][nf][2] * inv1), rna_tf32(o[mf][nf][3] * inv1) };
            *(float2*)(Orow + col) = lo;
            *(float2*)(Orow + 8 * 2048 + col) = hi;
        }
    }
}

// ---------------------------------------------------------------------------
extern "C" void kernel_launch(void* const* d_in, const int* in_sizes, int n_in,
                              void* d_out, int out_size)
{
    const float*    x            = (const float*)d_in[0];
    const unsigned* layer_idx    = (const unsigned*)d_in[1];
    const float*    lambda_param = (const float*)d_in[2];

    const float *Wq1, *bq1, *Wk1, *bk1, *Wv1, *bv1, *Wo1, *bo1;
    const float *Wq2, *bq2, *Wk2, *bk2, *Wv2, *bv2, *Wo2, *bo2;

    bool sig_order = (in_sizes[4] < 100000);
    if (!sig_order) {
        Wq1 = (const float*)d_in[3];  Wk1 = (const float*)d_in[4];
        Wv1 = (const float*)d_in[5];  Wo1 = (const float*)d_in[6];
        bq1 = (const float*)d_in[7];  bk1 = (const float*)d_in[8];
        bv1 = (const float*)d_in[9];  bo1 = (const float*)d_in[10];
        Wq2 = (const float*)d_in[11]; Wk2 = (const float*)d_in[12];
        Wv2 = (const float*)d_in[13]; Wo2 = (const float*)d_in[14];
        bq2 = (const float*)d_in[15]; bk2 = (const float*)d_in[16];
        bv2 = (const float*)d_in[17]; bo2 = (const float*)d_in[18];
    } else {
        Wq1 = (const float*)d_in[3];  bq1 = (const float*)d_in[4];
        Wk1 = (const float*)d_in[5];  bk1 = (const float*)d_in[6];
        Wv1 = (const float*)d_in[7];  bv1 = (const float*)d_in[8];
        Wo1 = (const float*)d_in[9];  bo1 = (const float*)d_in[10];
        Wq2 = (const float*)d_in[11]; bq2 = (const float*)d_in[12];
        Wk2 = (const float*)d_in[13]; bk2 = (const float*)d_in[14];
        Wv2 = (const float*)d_in[15]; bv2 = (const float*)d_in[16];
        Wo2 = (const float*)d_in[17]; bo2 = (const float*)d_in[18];
    }
    const float* Wp = (const float*)d_in[19];
    const float* bp = (const float*)d_in[20];

    float* s = nullptr;
    cudaGetSymbolAddress((void**)&s, g_scratch);
    float* XR  = s;                            // [4096,1024] rounded x
    float* WR  = s + 1 * CHUNK;                // 9 x [1024,1024] rounded weights
    float* QKV = s + 1 * CHUNK + 9 * WCH;      // [4096,6144]
    float* OB  = QKV + 6 * CHUNK;              // [4096,2048]
    float* TB  = OB + 2 * CHUNK;               // [4096,2048]

    const int GEMM_SMEM01 = 3 * (ASZ + BSZ_) * 4;        // 156672
    const int GEMM_SMEM2  = 3 * (2 * ASZ + BSZ_) * 4;    // 211968

    cudaFuncSetAttribute(gemm_mma<0>, cudaFuncAttributeMaxDynamicSharedMemorySize, GEMM_SMEM01);
    cudaFuncSetAttribute(gemm_mma<1>, cudaFuncAttributeMaxDynamicSharedMemorySize, GEMM_SMEM01);
    cudaFuncSetAttribute(gemm_mma<2>, cudaFuncAttributeMaxDynamicSharedMemorySize, GEMM_SMEM2);
    cudaFuncSetAttribute(flash_mma,   cudaFuncAttributeMaxDynamicSharedMemorySize, ATT_SMEM);

    // prep: round x + 9 weights (order: Wq1 Wk1 Wv1 Wq2 Wk2 Wv2 Wo1 Wo2 Wp)
    Ptrs10 src = {{ (const float4*)x,
                    (const float4*)Wq1, (const float4*)Wk1, (const float4*)Wv1,
                    (const float4*)Wq2, (const float4*)Wk2, (const float4*)Wv2,
                    (const float4*)Wo1, (const float4*)Wo2, (const float4*)Wp }};
    prep_round<<<2048, 256>>>(src, (float4*)s);

    // fused QKV projection: XR x 6 weights -> [4096,6144]
    Ptrs6 wqkv = {{ WR + 0 * WCH, WR + 1 * WCH, WR + 2 * WCH,
                    WR + 3 * WCH, WR + 4 * WCH, WR + 5 * WCH }};
    Ptrs6 bqkv = {{ bq1, bk1, bv1, bq2, bk2, bv2 }};
    gemm_mma<0><<<dim3(24, 32), 256, GEMM_SMEM01>>>(XR, wqkv, bqkv, QKV, 6144, 1024, 6144,
                                                    nullptr, nullptr);

    // attention, both branches
    flash_mma<<<dim3(Ssz / 256, Bsz * Hsz, 2), 256, ATT_SMEM>>>(QKV, OB);

    // fused output projections (block-diagonal A)
    Ptrs6 wwo = {{ WR + 6 * WCH, WR + 7 * WCH, nullptr, nullptr, nullptr, nullptr }};
    Ptrs6 bwo = {{ bo1, bo2, nullptr, nullptr, nullptr, nullptr }};
    gemm_mma<1><<<dim3(8, 32), 256, GEMM_SMEM01>>>(OB, wwo, bwo, TB, 2048, 2048, 2048,
                                                   nullptr, nullptr);

    // final projection with fused diff: (T1 - lam*T2) @ Wp + bp -> d_out
    Ptrs6 wp  = {{ WR + 8 * WCH, nullptr, nullptr, nullptr, nullptr, nullptr }};
    Ptrs6 bpp = {{ bp, nullptr, nullptr, nullptr, nullptr, nullptr }};
    gemm_mma<2><<<dim3(4, 32), 256, GEMM_SMEM2>>>(TB, wp, bpp, (float*)d_out, 1024, 2048, 1024,
                                                  lambda_param, layer_idx);
}

// round 7
// speedup vs baseline: 1.5875x; 1.5503x over previous
#include <cuda_runtime.h>
#include <cuda_fp16.h>
#include <math.h>
#include <stdint.h>

#define Bsz 2
#define Ssz 2048
#define Hsz 16
#define Msz 4096

// fp16 scratch: XH 8MB | WT 18MB | QKV 48MB | OB 16MB | TB 16MB
#define OFF_XH  0ull
#define OFF_WT  8388608ull
#define OFF_QKV 27262976ull
#define OFF_OB  77594624ull
#define OFF_TB  94371840ull
__device__ __align__(1024) unsigned char g_scratch[111149056ull];

// ---------------------------------------------------------------------------
// helpers
// ---------------------------------------------------------------------------
__device__ __forceinline__ uint32_t cvta_smem(const void* p) {
    uint32_t a;
    asm("{ .reg .u64 t; cvta.to.shared.u64 t, %1; cvt.u32.u64 %0, t; }"
        : "=r"(a) : "l"(p));
    return a;
}
__device__ __forceinline__ void cp16(uint32_t dst, const void* src) {
    asm volatile("cp.async.cg.shared.global [%0], [%1], 16;" :: "r"(dst), "l"(src));
}
__device__ __forceinline__ void cp_commit() { asm volatile("cp.async.commit_group;"); }
template <int N>
__device__ __forceinline__ void cp_wait() { asm volatile("cp.async.wait_group %0;" :: "n"(N)); }

// pack 2 floats -> fp16x2 (RN)
__device__ __forceinline__ uint32_t f2h2(float lo, float hi) {
    uint32_t r;
    asm("cvt.rn.f16x2.f32 %0, %2, %1;" : "=r"(r) : "f"(lo), "f"(hi));
    return r;
}
__device__ __forceinline__ float2 h2f2(uint32_t u) {
    __half2 h = *reinterpret_cast<__half2*>(&u);
    return __half22float2(h);
}

// mma m16n8k16 fp16 in, fp32 accum
__device__ __forceinline__ void mma16(float c[4], const uint32_t a[4],
                                      uint32_t b0, uint32_t b1) {
    asm volatile(
        "mma.sync.aligned.m16n8k16.row.col.f32.f16.f16.f32 "
        "{%0,%1,%2,%3}, {%4,%5,%6,%7}, {%8,%9}, {%0,%1,%2,%3};"
        : "+f"(c[0]), "+f"(c[1]), "+f"(c[2]), "+f"(c[3])
        : "r"(a[0]), "r"(a[1]), "r"(a[2]), "r"(a[3]), "r"(b0), "r"(b1));
}
__device__ __forceinline__ void ldm_x4(uint32_t r[4], uint32_t addr) {
    asm volatile("ldmatrix.sync.aligned.m8n8.x4.shared.b16 {%0,%1,%2,%3}, [%4];"
        : "=r"(r[0]), "=r"(r[1]), "=r"(r[2]), "=r"(r[3]) : "r"(addr));
}
__device__ __forceinline__ void ldm_x4t(uint32_t r[4], uint32_t addr) {
    asm volatile("ldmatrix.sync.aligned.m8n8.x4.trans.shared.b16 {%0,%1,%2,%3}, [%4];"
        : "=r"(r[0]), "=r"(r[1]), "=r"(r[2]), "=r"(r[3]) : "r"(addr));
}

struct PtrsW { const float* p[9]; };
struct PtrsB { const float* p[6]; };
struct HPtrs6 { const __half* p[6]; };

// ---------------------------------------------------------------------------
// prep 1: x fp32 -> fp16
// ---------------------------------------------------------------------------
__global__ void conv_x(const float4* __restrict__ in, uint4* __restrict__ out)
{
    const int n8 = Msz * 1024 / 8;   // 524288
    int i = blockIdx.x * blockDim.x + threadIdx.x;
    int st = gridDim.x * blockDim.x;
    for (; i < n8; i += st) {
        float4 v0 = in[2 * i], v1 = in[2 * i + 1];
        uint4 o;
        o.x = f2h2(v0.x, v0.y); o.y = f2h2(v0.z, v0.w);
        o.z = f2h2(v1.x, v1.y); o.w = f2h2(v1.z, v1.w);
        out[i] = o;
    }
}

// ---------------------------------------------------------------------------
// prep 2: transpose+convert 9 weights [1024 k][1024 n] f32 -> [1024 n][1024 k] fp16
// ---------------------------------------------------------------------------
__global__ __launch_bounds__(256)
void trans_w(PtrsW src, uint32_t* __restrict__ dst)
{
    __shared__ float tsm[32][33];
    const int z = blockIdx.z;
    const float* W = src.p[z];
    uint32_t* out = dst + (size_t)z * (1024 * 512);
    const int bx = blockIdx.x * 32, by = blockIdx.y * 32;
    const int x = threadIdx.x, y = threadIdx.y;
    for (int i = y; i < 32; i += 8)
        tsm[i][x] = W[(size_t)(by + i) * 1024 + bx + x];
    __syncthreads();
    int tid = y * 32 + x;
#pragma unroll
    for (int s = 0; s < 2; s++) {
        int idx = tid + s * 256;
        int row = idx >> 4, p = idx & 15;
        out[(size_t)(bx + row) * 512 + (by >> 1) + p] =
            f2h2(tsm[2 * p][row], tsm[2 * p + 1][row]);
    }
}

// ---------------------------------------------------------------------------
// fp16 mma.sync GEMM, CTA tile 128x256, BK=32, 8 warps (warp tile 64x64).
// ---------------------------------------------------------------------------
#define AW 20
#define BW 20
#define A_U (128 * AW)   // 2560 u32
#define B_U (256 * BW)   // 5120 u32

template <int VAR>
__global__ __launch_bounds__(256, 1)
void gemm_h(const __half* __restrict__ A, HPtrs6 Bp, PtrsB biasP,
            void* __restrict__ Cout, int N, int lda, int ldc,
            const float* __restrict__ lambda_param,
            const unsigned* __restrict__ layer_idx_bits)
{
    constexpr int A_ST = (VAR == 2) ? 2 * A_U : A_U;
    constexpr int STG = A_ST + B_U;
    extern __shared__ uint32_t smu[];
    const uint32_t sbase = cvta_smem(smu);

    const int tid = threadIdx.x;
    const int lane = tid & 31;
    const int g = lane >> 2, t = lane & 3;
    const int wid = tid >> 5;
    const int wm = wid >> 2, wn = wid & 3;
    const int m0 = blockIdx.y * 128, n0 = blockIdx.x * 256;
    const int j = n0 >> 10, nn = n0 & 1023;
    const int aoff = (VAR == 1) ? (j << 10) : 0;

    float lam = 0.f;
    if (VAR == 2) {
        unsigned bits = *layer_idx_bits;
        float lf = (bits < 10000u) ? (float)bits : __uint_as_float(bits);
        float e = __expf(-0.3f * fmaxf(lf - 1.0f, 0.0f));
        lam = fminf(fmaxf((0.8f - 0.6f * e) * lambda_param[0], 0.1f), 0.9f);
    }

    const __half* Bj = Bp.p[j];
    float c[4][8][4] = {};

    auto loadTile = [&](int stg, int kt) {
        uint32_t sa = sbase + (uint32_t)(stg * STG) * 4u;
        uint32_t sb = sa + (uint32_t)A_ST * 4u;
#pragma unroll
        for (int i = 0; i < 2; i++) {
            int idx = tid + i * 256;
            int row = idx >> 2, ch = idx & 3;
            const __half* src = A + (size_t)(m0 + row) * lda + aoff + kt * 32 + ch * 8;
            cp16(sa + (uint32_t)(row * AW + ch * 4) * 4u, src);
            if (VAR == 2)
                cp16(sa + (uint32_t)(A_U + row * AW + ch * 4) * 4u, src + 1024);
        }
#pragma unroll
        for (int i = 0; i < 4; i++) {
            int idx = tid + i * 256;
            int row = idx >> 2, ch = idx & 3;
            cp16(sb + (uint32_t)(row * BW + ch * 4) * 4u,
                 Bj + (size_t)(nn + row) * 1024 + kt * 32 + ch * 8);
        }
        cp_commit();
    };

    const int T = 32;
    loadTile(0, 0); loadTile(1, 1);

    for (int kt = 0; kt < T; kt++) {
        const int stg = kt % 3;
        if (kt < T - 1) cp_wait<1>(); else cp_wait<0>();
        __syncthreads();
        if (kt + 2 < T) loadTile((kt + 2) % 3, kt + 2);

        const uint32_t* Au = smu + stg * STG;
        const uint32_t* Bu = Au + A_ST;
#pragma unroll
        for (int kf = 0; kf < 2; kf++) {
            uint32_t a[4][4];
#pragma unroll
            for (int mf = 0; mf < 4; mf++) {
                int rb = wm * 64 + mf * 16;
#pragma unroll
                for (int q = 0; q < 4; q++) {
                    int r = rb + g + ((q & 1) ? 8 : 0);
                    int kp = kf * 8 + t + ((q >> 1) ? 4 : 0);
                    uint32_t u = Au[r * AW + kp];
                    if (VAR == 2) {
                        float2 fu = h2f2(u), fv = h2f2(Au[A_U + r * AW + kp]);
                        a[mf][q] = f2h2(fmaf(-lam, fv.x, fu.x), fmaf(-lam, fv.y, fu.y));
                    } else a[mf][q] = u;
                }
            }
#pragma unroll
            for (int nf = 0; nf < 8; nf++) {
                int n = wn * 64 + nf * 8 + g;
                uint32_t b0 = Bu[n * BW + kf * 8 + t];
                uint32_t b1 = Bu[n * BW + kf * 8 + 4 + t];
#pragma unroll
                for (int mf = 0; mf < 4; mf++)
                    mma16(c[mf][nf], a[mf], b0, b1);
            }
        }
    }

    const float* bb = biasP.p[j] + nn;
#pragma unroll
    for (int mf = 0; mf < 4; mf++) {
        int r0 = m0 + wm * 64 + mf * 16 + g;
#pragma unroll
        for (int nf = 0; nf < 8; nf++) {
            int cl = wn * 64 + nf * 8 + 2 * t;
            float bv0 = bb[cl], bv1 = bb[cl + 1];
            float v00 = c[mf][nf][0] + bv0, v01 = c[mf][nf][1] + bv1;
            float v10 = c[mf][nf][2] + bv0, v11 = c[mf][nf][3] + bv1;
            if (VAR == 2) {
                float* C = (float*)Cout;
                *(float2*)(C + (size_t)r0 * ldc + n0 + cl) = make_float2(v00, v01);
                *(float2*)(C + (size_t)(r0 + 8) * ldc + n0 + cl) = make_float2(v10, v11);
            } else {
                uint32_t* C = (uint32_t*)Cout;
                int lp = ldc >> 1;
                C[(size_t)r0 * lp + ((n0 + cl) >> 1)] = f2h2(v00, v01);
                C[(size_t)(r0 + 8) * lp + ((n0 + cl) >> 1)] = f2h2(v10, v11);
            }
        }
    }
}

// ---------------------------------------------------------------------------
// fp16 flash attention. QKV [M,6144] fp16, O [M,2048] fp16.
// ---------------------------------------------------------------------------
#define KWu 36
#define KSTGu (64 * KWu)
#define ATT_SMEM ((4 * KSTGu + 256 * KWu) * 4)   // 73728 B

__global__ __launch_bounds__(256, 1)
void flash_h(const __half* __restrict__ QKV, __half* __restrict__ OB)
{
    extern __shared__ uint32_t smu[];
    const uint32_t sbase = cvta_smem(smu);
    const uint32_t sK = sbase;
    const uint32_t sV = sbase + (uint32_t)(2 * KSTGu) * 4u;
    const uint32_t sP = sbase + (uint32_t)(4 * KSTGu) * 4u;
    uint32_t* Pu = smu + 4 * KSTGu;

    const int tid = threadIdx.x;
    const int w = tid >> 5, lane = tid & 31;
    const int g = lane >> 2, t = lane & 3;
    const int sel = lane >> 3, r8 = lane & 7;
    const int b = blockIdx.y >> 4, h = blockIdx.y & 15, z = blockIdx.z;
    const int q0 = blockIdx.x * 256;
    const size_t ld = 6144;

    const size_t base = (size_t)b * Ssz * ld + (size_t)z * 3072 + h * 64;
    const __half* Kg = QKV + base + 1024;
    const __half* Vg = QKV + base + 2048;

    const __half2 scq = __float2half2_rn(0.125f);
    uint32_t qf[2][4][4];
#pragma unroll
    for (int mf = 0; mf < 2; mf++) {
#pragma unroll
        for (int q = 0; q < 4; q++) {
            int row = q0 + w * 32 + mf * 16 + g + ((q & 1) ? 8 : 0);
            const __half2* Q2 = (const __half2*)QKV + ((base + (size_t)row * ld) >> 1);
#pragma unroll
            for (int kf = 0; kf < 4; kf++) {
                __half2 v = __hmul2(Q2[kf * 8 + t + ((q >> 1) ? 4 : 0)], scq);
                qf[mf][kf][q] = *(uint32_t*)&v;
            }
        }
    }

    float o[2][8][4] = {};
    float mm[2][2] = { {-1e30f, -1e30f}, {-1e30f, -1e30f} };
    float ll[2][2] = {};

    auto loadKV = [&](int buf, int tile) {
#pragma unroll
        for (int i = 0; i < 2; i++) {
            int idx = tid + i * 256;
            int row = idx >> 3, ch = idx & 7;
            size_t off = (size_t)(tile * 64 + row) * ld + ch * 8;
            cp16(sK + (uint32_t)(buf * KSTGu + row * KWu + ch * 4) * 4u, Kg + off);
            cp16(sV + (uint32_t)(buf * KSTGu + row * KWu + ch * 4) * 4u, Vg + off);
        }
        cp_commit();
    };

    const int NT = Ssz / 64;
    loadKV(0, 0);

    const int rowB = (sel >= 2) ? 8 : 0, colB = (sel & 1) ? 4 : 0;
    const int rowA = (sel & 1) ? 8 : 0, colA = (sel >= 2) ? 4 : 0;

    for (int tile = 0; tile < NT; tile++) {
        const int buf = tile & 1;
        if (tile + 1 < NT) { loadKV(buf ^ 1, tile + 1); cp_wait<1>(); }
        else cp_wait<0>();
        __syncthreads();

        const uint32_t sKb = sK + (uint32_t)(buf * KSTGu) * 4u;
        const uint32_t sVb = sV + (uint32_t)(buf * KSTGu) * 4u;

        float s[2][8][4] = {};
#pragma unroll
        for (int kf = 0; kf < 4; kf++) {
#pragma unroll
            for (int np = 0; np < 4; np++) {
                uint32_t kb[4];
                ldm_x4(kb, sKb + (uint32_t)((np * 16 + rowB + r8) * KWu + kf * 8 + colB) * 4u);
                mma16(s[0][2 * np],     qf[0][kf], kb[0], kb[1]);
                mma16(s[0][2 * np + 1], qf[0][kf], kb[2], kb[3]);
                mma16(s[1][2 * np],     qf[1][kf], kb[0], kb[1]);
                mma16(s[1][2 * np + 1], qf[1][kf], kb[2], kb[3]);
            }
        }

#pragma unroll
        for (int mf = 0; mf < 2; mf++) {
            float tmax0 = -1e30f, tmax1 = -1e30f;
#pragma unroll
            for (int nf = 0; nf < 8; nf++) {
                tmax0 = fmaxf(tmax0, fmaxf(s[mf][nf][0], s[mf][nf][1]));
                tmax1 = fmaxf(tmax1, fmaxf(s[mf][nf][2], s[mf][nf][3]));
            }
            tmax0 = fmaxf(tmax0, __shfl_xor_sync(0xffffffffu, tmax0, 1));
            tmax0 = fmaxf(tmax0, __shfl_xor_sync(0xffffffffu, tmax0, 2));
            tmax1 = fmaxf(tmax1, __shfl_xor_sync(0xffffffffu, tmax1, 1));
            tmax1 = fmaxf(tmax1, __shfl_xor_sync(0xffffffffu, tmax1, 2));

            float mn0 = fmaxf(mm[mf][0], tmax0), mn1 = fmaxf(mm[mf][1], tmax1);
            float al0 = __expf(mm[mf][0] - mn0), al1 = __expf(mm[mf][1] - mn1);

            const int pr0 = (w * 32 + mf * 16 + g) * KWu;
            const int pr1 = pr0 + 8 * KWu;
            float rs0 = 0.f, rs1 = 0.f;
#pragma unroll
            for (int nf = 0; nf < 8; nf++) {
                float p0 = __expf(s[mf][nf][0] - mn0);
                float p1 = __expf(s[mf][nf][1] - mn0);
                float p2 = __expf(s[mf][nf][2] - mn1);
                float p3 = __expf(s[mf][nf][3] - mn1);
                rs0 += p0 + p1; rs1 += p2 + p3;
                Pu[pr0 + nf * 4 + t] = f2h2(p0, p1);
                Pu[pr1 + nf * 4 + t] = f2h2(p2, p3);
            }
            rs0 += __shfl_xor_sync(0xffffffffu, rs0, 1);
            rs0 += __shfl_xor_sync(0xffffffffu, rs0, 2);
            rs1 += __shfl_xor_sync(0xffffffffu, rs1, 1);
            rs1 += __shfl_xor_sync(0xffffffffu, rs1, 2);
            ll[mf][0] = ll[mf][0] * al0 + rs0;
            ll[mf][1] = ll[mf][1] * al1 + rs1;
            mm[mf][0] = mn0; mm[mf][1] = mn1;
#pragma unroll
            for (int nf = 0; nf < 8; nf++) {
                o[mf][nf][0] *= al0; o[mf][nf][1] *= al0;
                o[mf][nf][2] *= al1; o[mf][nf][3] *= al1;
            }
        }
        __syncwarp();

#pragma unroll
        for (int kf = 0; kf < 4; kf++) {
            uint32_t a0[4], a1[4];
            ldm_x4(a0, sP + (uint32_t)((w * 32 + rowA + r8) * KWu + kf * 8 + colA) * 4u);
            ldm_x4(a1, sP + (uint32_t)((w * 32 + 16 + rowA + r8) * KWu + kf * 8 + colA) * 4u);
#pragma unroll
            for (int np = 0; np < 4; np++) {
                uint32_t vb[4];
                ldm_x4t(vb, sVb + (uint32_t)((kf * 16 + rowA + r8) * KWu + np * 8 + colA) * 4u);
                mma16(o[0][2 * np],     a0, vb[0], vb[1]);
                mma16(o[0][2 * np + 1], a0, vb[2], vb[3]);
                mma16(o[1][2 * np],     a1, vb[0], vb[1]);
                mma16(o[1][2 * np + 1], a1, vb[2], vb[3]);
            }
        }
        __syncthreads();
    }

    uint32_t* O2 = (uint32_t*)OB;
#pragma unroll
    for (int mf = 0; mf < 2; mf++) {
        float inv0 = 1.f / ll[mf][0], inv1 = 1.f / ll[mf][1];
        int row = q0 + w * 32 + mf * 16 + g;
        size_t rb0 = (size_t)(b * Ssz + row) * 1024 + z * 512 + h * 32;
        size_t rb1 = rb0 + 8 * 1024;
#pragma unroll
        for (int nf = 0; nf < 8; nf++) {
            O2[rb0 + nf * 4 + t] = f2h2(o[mf][nf][0] * inv0, o[mf][nf][1] * inv0);
            O2[rb1 + nf * 4 + t] = f2h2(o[mf][nf][2] * inv1, o[mf][nf][3] * inv1);
        }
    }
}

// ---------------------------------------------------------------------------
extern "C" void kernel_launch(void* const* d_in, const int* in_sizes, int n_in,
                              void* d_out, int out_size)
{
    const float*    x            = (const float*)d_in[0];
    const unsigned* layer_idx    = (const unsigned*)d_in[1];
    const float*    lambda_param = (const float*)d_in[2];

    const float *Wq1, *bq1, *Wk1, *bk1, *Wv1, *bv1, *Wo1, *bo1;
    const float *Wq2, *bq2, *Wk2, *bk2, *Wv2, *bv2, *Wo2, *bo2;

    bool sig_order = (in_sizes[4] < 100000);
    if (!sig_order) {
        Wq1 = (const float*)d_in[3];  Wk1 = (const float*)d_in[4];
        Wv1 = (const float*)d_in[5];  Wo1 = (const float*)d_in[6];
        bq1 = (const float*)d_in[7];  bk1 = (const float*)d_in[8];
        bv1 = (const float*)d_in[9];  bo1 = (const float*)d_in[10];
        Wq2 = (const float*)d_in[11]; Wk2 = (const float*)d_in[12];
        Wv2 = (const float*)d_in[13]; Wo2 = (const float*)d_in[14];
        bq2 = (const float*)d_in[15]; bk2 = (const float*)d_in[16];
        bv2 = (const float*)d_in[17]; bo2 = (const float*)d_in[18];
    } else {
        Wq1 = (const float*)d_in[3];  bq1 = (const float*)d_in[4];
        Wk1 = (const float*)d_in[5];  bk1 = (const float*)d_in[6];
        Wv1 = (const float*)d_in[7];  bv1 = (const float*)d_in[8];
        Wo1 = (const float*)d_in[9];  bo1 = (const float*)d_in[10];
        Wq2 = (const float*)d_in[11]; bq2 = (const float*)d_in[12];
        Wk2 = (const float*)d_in[13]; bk2 = (const float*)d_in[14];
        Wv2 = (const float*)d_in[15]; bv2 = (const float*)d_in[16];
        Wo2 = (const float*)d_in[17]; bo2 = (const float*)d_in[18];
    }
    const float* Wp = (const float*)d_in[19];
    const float* bp = (const float*)d_in[20];

    unsigned char* sc = nullptr;
    cudaGetSymbolAddress((void**)&sc, g_scratch);
    __half* XH  = (__half*)(sc + OFF_XH);
    __half* WT  = (__half*)(sc + OFF_WT);
    __half* QKV = (__half*)(sc + OFF_QKV);
    __half* OB  = (__half*)(sc + OFF_OB);
    __half* TB  = (__half*)(sc + OFF_TB);

    const int SMEM01 = 3 * (A_U + B_U) * 4;       // 92160
    const int SMEM2  = 3 * (2 * A_U + B_U) * 4;   // 122880

    cudaFuncSetAttribute(gemm_h<0>, cudaFuncAttributeMaxDynamicSharedMemorySize, SMEM01);
    cudaFuncSetAttribute(gemm_h<1>, cudaFuncAttributeMaxDynamicSharedMemorySize, SMEM01);
    cudaFuncSetAttribute(gemm_h<2>, cudaFuncAttributeMaxDynamicSharedMemorySize, SMEM2);
    cudaFuncSetAttribute(flash_h,   cudaFuncAttributeMaxDynamicSharedMemorySize, ATT_SMEM);

    conv_x<<<512, 256>>>((const float4*)x, (uint4*)XH);
    PtrsW srcW = {{ Wq1, Wk1, Wv1, Wq2, Wk2, Wv2, Wo1, Wo2, Wp }};
    trans_w<<<dim3(32, 32, 9), dim3(32, 8)>>>(srcW, (uint32_t*)WT);

    HPtrs6 wqkv = {{ WT + 0ull * 1048576, WT + 1ull * 1048576, WT + 2ull * 1048576,
                     WT + 3ull * 1048576, WT + 4ull * 1048576, WT + 5ull * 1048576 }};
    PtrsB bqkv = {{ bq1, bk1, bv1, bq2, bk2, bv2 }};
    gemm_h<0><<<dim3(24, 32), 256, SMEM01>>>(XH, wqkv, bqkv, QKV, 6144, 1024, 6144,
                                             nullptr, nullptr);

    flash_h<<<dim3(Ssz / 256, Bsz * Hsz, 2), 256, ATT_SMEM>>>(QKV, OB);

    HPtrs6 wwo = {{ WT + 6ull * 1048576, WT + 7ull * 1048576, nullptr, nullptr, nullptr, nullptr }};
    PtrsB bwo = {{ bo1, bo2, nullptr, nullptr, nullptr, nullptr }};
    gemm_h<1><<<dim3(8, 32), 256, SMEM01>>>(OB, wwo, bwo, TB, 2048, 2048, 2048,
                                            nullptr, nullptr);

    HPtrs6 wp  = {{ WT + 8ull * 1048576, nullptr, nullptr, nullptr, nullptr, nullptr }};
    PtrsB bpp = {{ bp, nullptr, nullptr, nullptr, nullptr, nullptr }};
    gemm_h<2><<<dim3(4, 32), 256, SMEM2>>>(TB, wp, bpp, d_out, 1024, 2048, 1024,
                                           lambda_param, layer_idx);
}

// round 8
// speedup vs baseline: 1.7217x; 1.0845x over previous
#include <cuda_runtime.h>
#include <cuda_fp16.h>
#include <math.h>
#include <stdint.h>

#define Bsz 2
#define Ssz 2048
#define Hsz 16
#define Msz 4096

// fp16 scratch: XH 8MB | WT 18MB | QKV 48MB | OB 16MB | TB 16MB
#define OFF_XH  0ull
#define OFF_WT  8388608ull
#define OFF_QKV 27262976ull
#define OFF_OB  77594624ull
#define OFF_TB  94371840ull
__device__ __align__(1024) unsigned char g_scratch[111149056ull];

// ---------------------------------------------------------------------------
// helpers
// ---------------------------------------------------------------------------
__device__ __forceinline__ uint32_t cvta_smem(const void* p) {
    uint32_t a;
    asm("{ .reg .u64 t; cvta.to.shared.u64 t, %1; cvt.u32.u64 %0, t; }"
        : "=r"(a) : "l"(p));
    return a;
}
__device__ __forceinline__ void cp16(uint32_t dst, const void* src) {
    asm volatile("cp.async.cg.shared.global [%0], [%1], 16;" :: "r"(dst), "l"(src));
}
__device__ __forceinline__ void cp_commit() { asm volatile("cp.async.commit_group;"); }
template <int N>
__device__ __forceinline__ void cp_wait() { asm volatile("cp.async.wait_group %0;" :: "n"(N)); }

__device__ __forceinline__ uint32_t f2h2(float lo, float hi) {
    uint32_t r;
    asm("cvt.rn.f16x2.f32 %0, %2, %1;" : "=r"(r) : "f"(lo), "f"(hi));
    return r;
}
__device__ __forceinline__ float2 h2f2(uint32_t u) {
    __half2 h = *reinterpret_cast<__half2*>(&u);
    return __half22float2(h);
}
__device__ __forceinline__ float ex2f(float x) {
    float r;
    asm("ex2.approx.f32 %0, %1;" : "=f"(r) : "f"(x));
    return r;
}

// mma m16n8k16 fp16 in, fp32 accum
__device__ __forceinline__ void mma16(float c[4], const uint32_t a[4],
                                      uint32_t b0, uint32_t b1) {
    asm volatile(
        "mma.sync.aligned.m16n8k16.row.col.f32.f16.f16.f32 "
        "{%0,%1,%2,%3}, {%4,%5,%6,%7}, {%8,%9}, {%0,%1,%2,%3};"
        : "+f"(c[0]), "+f"(c[1]), "+f"(c[2]), "+f"(c[3])
        : "r"(a[0]), "r"(a[1]), "r"(a[2]), "r"(a[3]), "r"(b0), "r"(b1));
}
__device__ __forceinline__ void ldm_x4(uint32_t r[4], uint32_t addr) {
    asm volatile("ldmatrix.sync.aligned.m8n8.x4.shared.b16 {%0,%1,%2,%3}, [%4];"
        : "=r"(r[0]), "=r"(r[1]), "=r"(r[2]), "=r"(r[3]) : "r"(addr));
}
__device__ __forceinline__ void ldm_x4t(uint32_t r[4], uint32_t addr) {
    asm volatile("ldmatrix.sync.aligned.m8n8.x4.trans.shared.b16 {%0,%1,%2,%3}, [%4];"
        : "=r"(r[0]), "=r"(r[1]), "=r"(r[2]), "=r"(r[3]) : "r"(addr));
}

struct PtrsW { const float* p[9]; };
struct PtrsB { const float* p[6]; };
struct HPtrs6 { const __half* p[6]; };

// ---------------------------------------------------------------------------
// prep 1: x fp32 -> fp16
// ---------------------------------------------------------------------------
__global__ void conv_x(const float4* __restrict__ in, uint4* __restrict__ out)
{
    const int n8 = Msz * 1024 / 8;
    int i = blockIdx.x * blockDim.x + threadIdx.x;
    int st = gridDim.x * blockDim.x;
    for (; i < n8; i += st) {
        float4 v0 = in[2 * i], v1 = in[2 * i + 1];
        uint4 o;
        o.x = f2h2(v0.x, v0.y); o.y = f2h2(v0.z, v0.w);
        o.z = f2h2(v1.x, v1.y); o.w = f2h2(v1.z, v1.w);
        out[i] = o;
    }
}

// ---------------------------------------------------------------------------
// prep 2: transpose+convert 9 weights [1024 k][1024 n] f32 -> [n][k] fp16
// ---------------------------------------------------------------------------
__global__ __launch_bounds__(256)
void trans_w(PtrsW src, uint32_t* __restrict__ dst)
{
    __shared__ float tsm[32][33];
    const int z = blockIdx.z;
    const float* W = src.p[z];
    uint32_t* out = dst + (size_t)z * (1024 * 512);
    const int bx = blockIdx.x * 32, by = blockIdx.y * 32;
    const int x = threadIdx.x, y = threadIdx.y;
    for (int i = y; i < 32; i += 8)
        tsm[i][x] = W[(size_t)(by + i) * 1024 + bx + x];
    __syncthreads();
    int tid = y * 32 + x;
#pragma unroll
    for (int s = 0; s < 2; s++) {
        int idx = tid + s * 256;
        int row = idx >> 4, p = idx & 15;
        out[(size_t)(bx + row) * 512 + (by >> 1) + p] =
            f2h2(tsm[2 * p][row], tsm[2 * p + 1][row]);
    }
}

// ---------------------------------------------------------------------------
// fp16 GEMM, CTA 128x256, BK=32, 8 warps (warp tile 64x64), 3-stage cp.async.
// VAR 0/1: ldmatrix fragment loads. VAR 2: scalar path with fused diff.
// ---------------------------------------------------------------------------
#define AW 20
#define BW 20
#define A_U (128 * AW)   // 2560 u32
#define B_U (256 * BW)   // 5120 u32

template <int VAR>
__global__ __launch_bounds__(256, 1)
void gemm_h(const __half* __restrict__ A, HPtrs6 Bp, PtrsB biasP,
            void* __restrict__ Cout, int N, int lda, int ldc,
            const float* __restrict__ lambda_param,
            const unsigned* __restrict__ layer_idx_bits)
{
    constexpr int A_ST = (VAR == 2) ? 2 * A_U : A_U;
    constexpr int STG = A_ST + B_U;
    extern __shared__ uint32_t smu[];
    const uint32_t sbase = cvta_smem(smu);

    const int tid = threadIdx.x;
    const int lane = tid & 31;
    const int g = lane >> 2, t = lane & 3;
    const int lrow = lane & 7, lsel = lane >> 3;
    const int wid = tid >> 5;
    const int wm = wid >> 2, wn = wid & 3;
    const int m0 = blockIdx.y * 128, n0 = blockIdx.x * 256;
    const int j = n0 >> 10, nn = n0 & 1023;
    const int aoffr = (VAR == 1) ? (j << 10) : 0;

    float lam = 0.f;
    if (VAR == 2) {
        unsigned bits = *layer_idx_bits;
        float lf = (bits < 10000u) ? (float)bits : __uint_as_float(bits);
        float e = __expf(-0.3f * fmaxf(lf - 1.0f, 0.0f));
        lam = fminf(fmaxf((0.8f - 0.6f * e) * lambda_param[0], 0.1f), 0.9f);
    }

    const __half* Bj = Bp.p[j];
    float c[4][8][4] = {};

    // ldmatrix per-thread offsets (bytes, relative to stage A / stage B start)
    const uint32_t aoff = (uint32_t)((wm * 64 + ((lsel & 1) ? 8 : 0) + lrow) * AW
                                     + ((lsel >> 1) ? 4 : 0)) * 4u;
    const uint32_t boff = (uint32_t)((wn * 64 + ((lsel >> 1) ? 8 : 0) + lrow) * BW
                                     + ((lsel & 1) ? 4 : 0)) * 4u;

    auto loadTile = [&](int stg, int kt) {
        uint32_t sa = sbase + (uint32_t)(stg * STG) * 4u;
        uint32_t sb = sa + (uint32_t)A_ST * 4u;
#pragma unroll
        for (int i = 0; i < 2; i++) {
            int idx = tid + i * 256;
            int row = idx >> 2, ch = idx & 3;
            const __half* src = A + (size_t)(m0 + row) * lda + aoffr + kt * 32 + ch * 8;
            cp16(sa + (uint32_t)(row * AW + ch * 4) * 4u, src);
            if (VAR == 2)
                cp16(sa + (uint32_t)(A_U + row * AW + ch * 4) * 4u, src + 1024);
        }
#pragma unroll
        for (int i = 0; i < 4; i++) {
            int idx = tid + i * 256;
            int row = idx >> 2, ch = idx & 3;
            cp16(sb + (uint32_t)(row * BW + ch * 4) * 4u,
                 Bj + (size_t)(nn + row) * 1024 + kt * 32 + ch * 8);
        }
        cp_commit();
    };

    const int T = 32;
    loadTile(0, 0); loadTile(1, 1);

    for (int kt = 0; kt < T; kt++) {
        const int stg = kt % 3;
        if (kt < T - 1) cp_wait<1>(); else cp_wait<0>();
        __syncthreads();
        if (kt + 2 < T) loadTile((kt + 2) % 3, kt + 2);

        if (VAR == 2) {
            const uint32_t* Au = smu + stg * STG;
            const uint32_t* Bu = Au + A_ST;
#pragma unroll
            for (int kf = 0; kf < 2; kf++) {
                uint32_t a[4][4];
#pragma unroll
                for (int mf = 0; mf < 4; mf++) {
                    int rb = wm * 64 + mf * 16;
#pragma unroll
                    for (int q = 0; q < 4; q++) {
                        int r = rb + g + ((q & 1) ? 8 : 0);
                        int kp = kf * 8 + t + ((q >> 1) ? 4 : 0);
                        float2 fu = h2f2(Au[r * AW + kp]);
                        float2 fv = h2f2(Au[A_U + r * AW + kp]);
                        a[mf][q] = f2h2(fmaf(-lam, fv.x, fu.x), fmaf(-lam, fv.y, fu.y));
                    }
                }
#pragma unroll
                for (int nf = 0; nf < 8; nf++) {
                    int n = wn * 64 + nf * 8 + g;
                    uint32_t b0 = Bu[n * BW + kf * 8 + t];
                    uint32_t b1 = Bu[n * BW + kf * 8 + 4 + t];
#pragma unroll
                    for (int mf = 0; mf < 4; mf++)
                        mma16(c[mf][nf], a[mf], b0, b1);
                }
            }
        } else {
            uint32_t aS = sbase + (uint32_t)(stg * STG) * 4u + aoff;
            uint32_t bS = sbase + (uint32_t)(stg * STG + A_ST) * 4u + boff;
#pragma unroll
            for (int kf = 0; kf < 2; kf++) {
                uint32_t a[4][4], bq[4][4];
#pragma unroll
                for (int mf = 0; mf < 4; mf++)
                    ldm_x4(a[mf], aS + (uint32_t)(mf * 16 * AW) * 4u + kf * 32u);
#pragma unroll
                for (int i = 0; i < 4; i++)
                    ldm_x4(bq[i], bS + (uint32_t)(i * 16 * BW) * 4u + kf * 32u);
#pragma unroll
                for (int i = 0; i < 4; i++)
#pragma unroll
                    for (int mf = 0; mf < 4; mf++) {
                        mma16(c[mf][2 * i],     a[mf], bq[i][0], bq[i][1]);
                        mma16(c[mf][2 * i + 1], a[mf], bq[i][2], bq[i][3]);
                    }
            }
        }
    }

    const float* bb = biasP.p[j] + nn;
#pragma unroll
    for (int mf = 0; mf < 4; mf++) {
        int r0 = m0 + wm * 64 + mf * 16 + g;
#pragma unroll
        for (int nf = 0; nf < 8; nf++) {
            int cl = wn * 64 + nf * 8 + 2 * t;
            float bv0 = bb[cl], bv1 = bb[cl + 1];
            float v00 = c[mf][nf][0] + bv0, v01 = c[mf][nf][1] + bv1;
            float v10 = c[mf][nf][2] + bv0, v11 = c[mf][nf][3] + bv1;
            if (VAR == 2) {
                float* C = (float*)Cout;
                *(float2*)(C + (size_t)r0 * ldc + n0 + cl) = make_float2(v00, v01);
                *(float2*)(C + (size_t)(r0 + 8) * ldc + n0 + cl) = make_float2(v10, v11);
            } else {
                uint32_t* C = (uint32_t*)Cout;
                int lp = ldc >> 1;
                C[(size_t)r0 * lp + ((n0 + cl) >> 1)] = f2h2(v00, v01);
                C[(size_t)(r0 + 8) * lp + ((n0 + cl) >> 1)] = f2h2(v10, v11);
            }
        }
    }
}

// ---------------------------------------------------------------------------
// fp16 flash attention, 16 q-rows/warp, 128 q-rows/CTA, 2 CTAs/SM.
// Q pre-scaled by log2(e)/8; softmax in exp2 domain (raw ex2.approx).
// ---------------------------------------------------------------------------
#define KWu 36
#define KSTGu (64 * KWu)
#define ATT_SMEM ((4 * KSTGu + 128 * KWu) * 4)   // 55296 B

__global__ __launch_bounds__(256, 2)
void flash_h(const __half* __restrict__ QKV, __half* __restrict__ OB)
{
    extern __shared__ uint32_t smu[];
    const uint32_t sbase = cvta_smem(smu);
    const uint32_t sK = sbase;
    const uint32_t sV = sbase + (uint32_t)(2 * KSTGu) * 4u;
    const uint32_t sP = sbase + (uint32_t)(4 * KSTGu) * 4u;
    uint32_t* Pu = smu + 4 * KSTGu;

    const int tid = threadIdx.x;
    const int w = tid >> 5, lane = tid & 31;
    const int g = lane >> 2, t = lane & 3;
    const int sel = lane >> 3, r8 = lane & 7;
    const int b = blockIdx.y >> 4, h = blockIdx.y & 15, z = blockIdx.z;
    const int q0 = blockIdx.x * 128;
    const size_t ld = 6144;

    const size_t base = (size_t)b * Ssz * ld + (size_t)z * 3072 + h * 64;
    const __half* Kg = QKV + base + 1024;
    const __half* Vg = QKV + base + 2048;

    // Q scale = log2(e)/8 : softmax runs in exp2 domain
    const __half2 scq = __float2half2_rn(0.18033688f);
    uint32_t qf[4][4];
#pragma unroll
    for (int q = 0; q < 4; q++) {
        int row = q0 + w * 16 + g + ((q & 1) ? 8 : 0);
        const __half2* Q2 = (const __half2*)QKV + ((base + (size_t)row * ld) >> 1);
#pragma unroll
        for (int kf = 0; kf < 4; kf++) {
            __half2 v = __hmul2(Q2[kf * 8 + t + ((q >> 1) ? 4 : 0)], scq);
            qf[kf][q] = *(uint32_t*)&v;
        }
    }

    float o[8][4] = {};
    float m0f = -1e30f, m1f = -1e30f, l0 = 0.f, l1 = 0.f;

    auto loadKV = [&](int buf, int tile) {
#pragma unroll
        for (int i = 0; i < 2; i++) {
            int idx = tid + i * 256;
            int row = idx >> 3, ch = idx & 7;
            size_t off = (size_t)(tile * 64 + row) * ld + ch * 8;
            cp16(sK + (uint32_t)(buf * KSTGu + row * KWu + ch * 4) * 4u, Kg + off);
            cp16(sV + (uint32_t)(buf * KSTGu + row * KWu + ch * 4) * 4u, Vg + off);
        }
        cp_commit();
    };

    const int NT = Ssz / 64;
    loadKV(0, 0);

    const int rowB = (sel >= 2) ? 8 : 0, colB = (sel & 1) ? 4 : 0;
    const int rowA = (sel & 1) ? 8 : 0, colA = (sel >= 2) ? 4 : 0;
    const int pr0 = (w * 16 + g) * KWu;
    const int pr1 = pr0 + 8 * KWu;

    for (int tile = 0; tile < NT; tile++) {
        const int buf = tile & 1;
        if (tile + 1 < NT) { loadKV(buf ^ 1, tile + 1); cp_wait<1>(); }
        else cp_wait<0>();
        __syncthreads();

        const uint32_t sKb = sK + (uint32_t)(buf * KSTGu) * 4u;
        const uint32_t sVb = sV + (uint32_t)(buf * KSTGu) * 4u;

        // S = Q K^T (16 x 64 per warp)
        float s[8][4] = {};
#pragma unroll
        for (int kf = 0; kf < 4; kf++) {
#pragma unroll
            for (int np = 0; np < 4; np++) {
                uint32_t kb[4];
                ldm_x4(kb, sKb + (uint32_t)((np * 16 + rowB + r8) * KWu + kf * 8 + colB) * 4u);
                mma16(s[2 * np],     qf[kf], kb[0], kb[1]);
                mma16(s[2 * np + 1], qf[kf], kb[2], kb[3]);
            }
        }

        // online softmax (exp2 domain)
        float tmax0 = -1e30f, tmax1 = -1e30f;
#pragma unroll
        for (int nf = 0; nf < 8; nf++) {
            tmax0 = fmaxf(tmax0, fmaxf(s[nf][0], s[nf][1]));
            tmax1 = fmaxf(tmax1, fmaxf(s[nf][2], s[nf][3]));
        }
        tmax0 = fmaxf(tmax0, __shfl_xor_sync(0xffffffffu, tmax0, 1));
        tmax0 = fmaxf(tmax0, __shfl_xor_sync(0xffffffffu, tmax0, 2));
        tmax1 = fmaxf(tmax1, __shfl_xor_sync(0xffffffffu, tmax1, 1));
        tmax1 = fmaxf(tmax1, __shfl_xor_sync(0xffffffffu, tmax1, 2));

        float mn0 = fmaxf(m0f, tmax0), mn1 = fmaxf(m1f, tmax1);
        float al0 = ex2f(m0f - mn0), al1 = ex2f(m1f - mn1);

        float rs0 = 0.f, rs1 = 0.f;
#pragma unroll
        for (int nf = 0; nf < 8; nf++) {
            float p0 = ex2f(s[nf][0] - mn0);
            float p1 = ex2f(s[nf][1] - mn0);
            float p2 = ex2f(s[nf][2] - mn1);
            float p3 = ex2f(s[nf][3] - mn1);
            rs0 += p0 + p1; rs1 += p2 + p3;
            Pu[pr0 + nf * 4 + t] = f2h2(p0, p1);
            Pu[pr1 + nf * 4 + t] = f2h2(p2, p3);
        }
        rs0 += __shfl_xor_sync(0xffffffffu, rs0, 1);
        rs0 += __shfl_xor_sync(0xffffffffu, rs0, 2);
        rs1 += __shfl_xor_sync(0xffffffffu, rs1, 1);
        rs1 += __shfl_xor_sync(0xffffffffu, rs1, 2);
        l0 = l0 * al0 + rs0;
        l1 = l1 * al1 + rs1;
        m0f = mn0; m1f = mn1;
#pragma unroll
        for (int nf = 0; nf < 8; nf++) {
            o[nf][0] *= al0; o[nf][1] *= al0;
            o[nf][2] *= al1; o[nf][3] *= al1;
        }
        __syncwarp();

        // O += P V (P a-frags via ldmatrix, V via ldmatrix.trans)
#pragma unroll
        for (int kf = 0; kf < 4; kf++) {
            uint32_t a0[4];
            ldm_x4(a0, sP + (uint32_t)((w * 16 + rowA + r8) * KWu + kf * 8 + colA) * 4u);
#pragma unroll
            for (int np = 0; np < 4; np++) {
                uint32_t vb[4];
                ldm_x4t(vb, sVb + (uint32_t)((kf * 16 + rowA + r8) * KWu + np * 8 + colA) * 4u);
                mma16(o[2 * np],     a0, vb[0], vb[1]);
                mma16(o[2 * np + 1], a0, vb[2], vb[3]);
            }
        }
        __syncthreads();
    }

    uint32_t* O2 = (uint32_t*)OB;
    float inv0 = 1.f / l0, inv1 = 1.f / l1;
    int row = q0 + w * 16 + g;
    size_t rb0 = (size_t)(b * Ssz + row) * 1024 + z * 512 + h * 32;
    size_t rb1 = rb0 + 8 * 1024;
#pragma unroll
    for (int nf = 0; nf < 8; nf++) {
        O2[rb0 + nf * 4 + t] = f2h2(o[nf][0] * inv0, o[nf][1] * inv0);
        O2[rb1 + nf * 4 + t] = f2h2(o[nf][2] * inv1, o[nf][3] * inv1);
    }
}

// ---------------------------------------------------------------------------
extern "C" void kernel_launch(void* const* d_in, const int* in_sizes, int n_in,
                              void* d_out, int out_size)
{
    const float*    x            = (const float*)d_in[0];
    const unsigned* layer_idx    = (const unsigned*)d_in[1];
    const float*    lambda_param = (const float*)d_in[2];

    const float *Wq1, *bq1, *Wk1, *bk1, *Wv1, *bv1, *Wo1, *bo1;
    const float *Wq2, *bq2, *Wk2, *bk2, *Wv2, *bv2, *Wo2, *bo2;

    bool sig_order = (in_sizes[4] < 100000);
    if (!sig_order) {
        Wq1 = (const float*)d_in[3];  Wk1 = (const float*)d_in[4];
        Wv1 = (const float*)d_in[5];  Wo1 = (const float*)d_in[6];
        bq1 = (const float*)d_in[7];  bk1 = (const float*)d_in[8];
        bv1 = (const float*)d_in[9];  bo1 = (const float*)d_in[10];
        Wq2 = (const float*)d_in[11]; Wk2 = (const float*)d_in[12];
        Wv2 = (const float*)d_in[13]; Wo2 = (const float*)d_in[14];
        bq2 = (const float*)d_in[15]; bk2 = (const float*)d_in[16];
        bv2 = (const float*)d_in[17]; bo2 = (const float*)d_in[18];
    } else {
        Wq1 = (const float*)d_in[3];  bq1 = (const float*)d_in[4];
        Wk1 = (const float*)d_in[5];  bk1 = (const float*)d_in[6];
        Wv1 = (const float*)d_in[7];  bv1 = (const float*)d_in[8];
        Wo1 = (const float*)d_in[9];  bo1 = (const float*)d_in[10];
        Wq2 = (const float*)d_in[11]; bq2 = (const float*)d_in[12];
        Wk2 = (const float*)d_in[13]; bk2 = (const float*)d_in[14];
        Wv2 = (const float*)d_in[15]; bv2 = (const float*)d_in[16];
        Wo2 = (const float*)d_in[17]; bo2 = (const float*)d_in[18];
    }
    const float* Wp = (const float*)d_in[19];
    const float* bp = (const float*)d_in[20];

    unsigned char* sc = nullptr;
    cudaGetSymbolAddress((void**)&sc, g_scratch);
    __half* XH  = (__half*)(sc + OFF_XH);
    __half* WT  = (__half*)(sc + OFF_WT);
    __half* QKV = (__half*)(sc + OFF_QKV);
    __half* OB  = (__half*)(sc + OFF_OB);
    __half* TB  = (__half*)(sc + OFF_TB);

    const int SMEM01 = 3 * (A_U + B_U) * 4;       // 92160
    const int SMEM2  = 3 * (2 * A_U + B_U) * 4;   // 122880

    cudaFuncSetAttribute(gemm_h<0>, cudaFuncAttributeMaxDynamicSharedMemorySize, SMEM01);
    cudaFuncSetAttribute(gemm_h<1>, cudaFuncAttributeMaxDynamicSharedMemorySize, SMEM01);
    cudaFuncSetAttribute(gemm_h<2>, cudaFuncAttributeMaxDynamicSharedMemorySize, SMEM2);
    cudaFuncSetAttribute(flash_h,   cudaFuncAttributeMaxDynamicSharedMemorySize, ATT_SMEM);

    conv_x<<<512, 256>>>((const float4*)x, (uint4*)XH);
    PtrsW srcW = {{ Wq1, Wk1, Wv1, Wq2, Wk2, Wv2, Wo1, Wo2, Wp }};
    trans_w<<<dim3(32, 32, 9), dim3(32, 8)>>>(srcW, (uint32_t*)WT);

    HPtrs6 wqkv = {{ WT + 0ull * 1048576, WT + 1ull * 1048576, WT + 2ull * 1048576,
                     WT + 3ull * 1048576, WT + 4ull * 1048576, WT + 5ull * 1048576 }};
    PtrsB bqkv = {{ bq1, bk1, bv1, bq2, bk2, bv2 }};
    gemm_h<0><<<dim3(24, 32), 256, SMEM01>>>(XH, wqkv, bqkv, QKV, 6144, 1024, 6144,
                                             nullptr, nullptr);

    flash_h<<<dim3(Ssz / 128, Bsz * Hsz, 2), 256, ATT_SMEM>>>(QKV, OB);

    HPtrs6 wwo = {{ WT + 6ull * 1048576, WT + 7ull * 1048576, nullptr, nullptr, nullptr, nullptr }};
    PtrsB bwo = {{ bo1, bo2, nullptr, nullptr, nullptr, nullptr }};
    gemm_h<1><<<dim3(8, 32), 256, SMEM01>>>(OB, wwo, bwo, TB, 2048, 2048, 2048,
                                            nullptr, nullptr);

    HPtrs6 wp  = {{ WT + 8ull * 1048576, nullptr, nullptr, nullptr, nullptr, nullptr }};
    PtrsB bpp = {{ bp, nullptr, nullptr, nullptr, nullptr, nullptr }};
    gemm_h<2><<<dim3(4, 32), 256, SMEM2>>>(TB, wp, bpp, d_out, 1024, 2048, 1024,
                                           lambda_param, layer_idx);
}

// round 9
// speedup vs baseline: 1.7817x; 1.0348x over previous
#include <cuda_runtime.h>
#include <cuda_fp16.h>
#include <math.h>
#include <stdint.h>

#define Bsz 2
#define Ssz 2048
#define Hsz 16
#define Msz 4096

// fp16 scratch: XH 8MB | WT 18MB | QKV 48MB | OB 16MB | TB 16MB
#define OFF_XH  0ull
#define OFF_WT  8388608ull
#define OFF_QKV 27262976ull
#define OFF_OB  77594624ull
#define OFF_TB  94371840ull
__device__ __align__(1024) unsigned char g_scratch[111149056ull];

// ---------------------------------------------------------------------------
// helpers
// ---------------------------------------------------------------------------
__device__ __forceinline__ uint32_t cvta_smem(const void* p) {
    uint32_t a;
    asm("{ .reg .u64 t; cvta.to.shared.u64 t, %1; cvt.u32.u64 %0, t; }"
        : "=r"(a) : "l"(p));
    return a;
}
__device__ __forceinline__ void cp16(uint32_t dst, const void* src) {
    asm volatile("cp.async.cg.shared.global [%0], [%1], 16;" :: "r"(dst), "l"(src));
}
__device__ __forceinline__ void cp_commit() { asm volatile("cp.async.commit_group;"); }
template <int N>
__device__ __forceinline__ void cp_wait() { asm volatile("cp.async.wait_group %0;" :: "n"(N)); }

__device__ __forceinline__ uint32_t f2h2(float lo, float hi) {
    uint32_t r;
    asm("cvt.rn.f16x2.f32 %0, %2, %1;" : "=r"(r) : "f"(lo), "f"(hi));
    return r;
}
__device__ __forceinline__ float2 h2f2(uint32_t u) {
    __half2 h = *reinterpret_cast<__half2*>(&u);
    return __half22float2(h);
}
__device__ __forceinline__ float ex2f(float x) {
    float r;
    asm("ex2.approx.f32 %0, %1;" : "=f"(r) : "f"(x));
    return r;
}

// mma m16n8k16 fp16 in, fp32 accum
__device__ __forceinline__ void mma16(float c[4], const uint32_t a[4],
                                      uint32_t b0, uint32_t b1) {
    asm volatile(
        "mma.sync.aligned.m16n8k16.row.col.f32.f16.f16.f32 "
        "{%0,%1,%2,%3}, {%4,%5,%6,%7}, {%8,%9}, {%0,%1,%2,%3};"
        : "+f"(c[0]), "+f"(c[1]), "+f"(c[2]), "+f"(c[3])
        : "r"(a[0]), "r"(a[1]), "r"(a[2]), "r"(a[3]), "r"(b0), "r"(b1));
}
__device__ __forceinline__ void ldm_x4(uint32_t r[4], uint32_t addr) {
    asm volatile("ldmatrix.sync.aligned.m8n8.x4.shared.b16 {%0,%1,%2,%3}, [%4];"
        : "=r"(r[0]), "=r"(r[1]), "=r"(r[2]), "=r"(r[3]) : "r"(addr));
}
__device__ __forceinline__ void ldm_x4t(uint32_t r[4], uint32_t addr) {
    asm volatile("ldmatrix.sync.aligned.m8n8.x4.trans.shared.b16 {%0,%1,%2,%3}, [%4];"
        : "=r"(r[0]), "=r"(r[1]), "=r"(r[2]), "=r"(r[3]) : "r"(addr));
}

struct PtrsW { const float* p[9]; };
struct PtrsB { const float* p[6]; };
struct HPtrs6 { const __half* p[6]; };

// ---------------------------------------------------------------------------
// prep 1: x fp32 -> fp16
// ---------------------------------------------------------------------------
__global__ void conv_x(const float4* __restrict__ in, uint4* __restrict__ out)
{
    const int n8 = Msz * 1024 / 8;
    int i = blockIdx.x * blockDim.x + threadIdx.x;
    int st = gridDim.x * blockDim.x;
    for (; i < n8; i += st) {
        float4 v0 = in[2 * i], v1 = in[2 * i + 1];
        uint4 o;
        o.x = f2h2(v0.x, v0.y); o.y = f2h2(v0.z, v0.w);
        o.z = f2h2(v1.x, v1.y); o.w = f2h2(v1.z, v1.w);
        out[i] = o;
    }
}

// ---------------------------------------------------------------------------
// prep 2: transpose+convert 9 weights [1024 k][1024 n] f32 -> [n][k] fp16
// ---------------------------------------------------------------------------
__global__ __launch_bounds__(256)
void trans_w(PtrsW src, uint32_t* __restrict__ dst)
{
    __shared__ float tsm[32][33];
    const int z = blockIdx.z;
    const float* W = src.p[z];
    uint32_t* out = dst + (size_t)z * (1024 * 512);
    const int bx = blockIdx.x * 32, by = blockIdx.y * 32;
    const int x = threadIdx.x, y = threadIdx.y;
    for (int i = y; i < 32; i += 8)
        tsm[i][x] = W[(size_t)(by + i) * 1024 + bx + x];
    __syncthreads();
    int tid = y * 32 + x;
#pragma unroll
    for (int s = 0; s < 2; s++) {
        int idx = tid + s * 256;
        int row = idx >> 4, p = idx & 15;
        out[(size_t)(bx + row) * 512 + (by >> 1) + p] =
            f2h2(tsm[2 * p][row], tsm[2 * p + 1][row]);
    }
}

// ---------------------------------------------------------------------------
// fp16 GEMM, CTA 128x256, BK=32, 8 warps (warp tile 64x64), 3-stage cp.async.
// VAR 0/1: ldmatrix fragment loads. VAR 2: scalar path with fused diff.
// ---------------------------------------------------------------------------
#define AW 20
#define BW 20
#define A_U (128 * AW)   // 2560 u32
#define B_U (256 * BW)   // 5120 u32

template <int VAR>
__global__ __launch_bounds__(256, 1)
void gemm_h(const __half* __restrict__ A, HPtrs6 Bp, PtrsB biasP,
            void* __restrict__ Cout, int N, int lda, int ldc,
            const float* __restrict__ lambda_param,
            const unsigned* __restrict__ layer_idx_bits)
{
    constexpr int A_ST = (VAR == 2) ? 2 * A_U : A_U;
    constexpr int STG = A_ST + B_U;
    extern __shared__ uint32_t smu[];
    const uint32_t sbase = cvta_smem(smu);

    const int tid = threadIdx.x;
    const int lane = tid & 31;
    const int g = lane >> 2, t = lane & 3;
    const int lrow = lane & 7, lsel = lane >> 3;
    const int wid = tid >> 5;
    const int wm = wid >> 2, wn = wid & 3;
    const int m0 = blockIdx.y * 128, n0 = blockIdx.x * 256;
    const int j = n0 >> 10, nn = n0 & 1023;
    const int aoffr = (VAR == 1) ? (j << 10) : 0;

    float lam = 0.f;
    if (VAR == 2) {
        unsigned bits = *layer_idx_bits;
        float lf = (bits < 10000u) ? (float)bits : __uint_as_float(bits);
        float e = __expf(-0.3f * fmaxf(lf - 1.0f, 0.0f));
        lam = fminf(fmaxf((0.8f - 0.6f * e) * lambda_param[0], 0.1f), 0.9f);
    }

    const __half* Bj = Bp.p[j];
    float c[4][8][4] = {};

    const uint32_t aoff = (uint32_t)((wm * 64 + ((lsel & 1) ? 8 : 0) + lrow) * AW
                                     + ((lsel >> 1) ? 4 : 0)) * 4u;
    const uint32_t boff = (uint32_t)((wn * 64 + ((lsel >> 1) ? 8 : 0) + lrow) * BW
                                     + ((lsel & 1) ? 4 : 0)) * 4u;

    auto loadTile = [&](int stg, int kt) {
        uint32_t sa = sbase + (uint32_t)(stg * STG) * 4u;
        uint32_t sb = sa + (uint32_t)A_ST * 4u;
#pragma unroll
        for (int i = 0; i < 2; i++) {
            int idx = tid + i * 256;
            int row = idx >> 2, ch = idx & 3;
            const __half* src = A + (size_t)(m0 + row) * lda + aoffr + kt * 32 + ch * 8;
            cp16(sa + (uint32_t)(row * AW + ch * 4) * 4u, src);
            if (VAR == 2)
                cp16(sa + (uint32_t)(A_U + row * AW + ch * 4) * 4u, src + 1024);
        }
#pragma unroll
        for (int i = 0; i < 4; i++) {
            int idx = tid + i * 256;
            int row = idx >> 2, ch = idx & 3;
            cp16(sb + (uint32_t)(row * BW + ch * 4) * 4u,
                 Bj + (size_t)(nn + row) * 1024 + kt * 32 + ch * 8);
        }
        cp_commit();
    };

    const int T = 32;
    loadTile(0, 0); loadTile(1, 1);

    for (int kt = 0; kt < T; kt++) {
        const int stg = kt % 3;
        if (kt < T - 1) cp_wait<1>(); else cp_wait<0>();
        __syncthreads();
        if (kt + 2 < T) loadTile((kt + 2) % 3, kt + 2);

        if (VAR == 2) {
            const uint32_t* Au = smu + stg * STG;
            const uint32_t* Bu = Au + A_ST;
#pragma unroll
            for (int kf = 0; kf < 2; kf++) {
                uint32_t a[4][4];
#pragma unroll
                for (int mf = 0; mf < 4; mf++) {
                    int rb = wm * 64 + mf * 16;
#pragma unroll
                    for (int q = 0; q < 4; q++) {
                        int r = rb + g + ((q & 1) ? 8 : 0);
                        int kp = kf * 8 + t + ((q >> 1) ? 4 : 0);
                        float2 fu = h2f2(Au[r * AW + kp]);
                        float2 fv = h2f2(Au[A_U + r * AW + kp]);
                        a[mf][q] = f2h2(fmaf(-lam, fv.x, fu.x), fmaf(-lam, fv.y, fu.y));
                    }
                }
#pragma unroll
                for (int nf = 0; nf < 8; nf++) {
                    int n = wn * 64 + nf * 8 + g;
                    uint32_t b0 = Bu[n * BW + kf * 8 + t];
                    uint32_t b1 = Bu[n * BW + kf * 8 + 4 + t];
#pragma unroll
                    for (int mf = 0; mf < 4; mf++)
                        mma16(c[mf][nf], a[mf], b0, b1);
                }
            }
        } else {
            uint32_t aS = sbase + (uint32_t)(stg * STG) * 4u + aoff;
            uint32_t bS = sbase + (uint32_t)(stg * STG + A_ST) * 4u + boff;
#pragma unroll
            for (int kf = 0; kf < 2; kf++) {
                uint32_t a[4][4], bq[4][4];
#pragma unroll
                for (int mf = 0; mf < 4; mf++)
                    ldm_x4(a[mf], aS + (uint32_t)(mf * 16 * AW) * 4u + kf * 32u);
#pragma unroll
                for (int i = 0; i < 4; i++)
                    ldm_x4(bq[i], bS + (uint32_t)(i * 16 * BW) * 4u + kf * 32u);
#pragma unroll
                for (int i = 0; i < 4; i++)
#pragma unroll
                    for (int mf = 0; mf < 4; mf++) {
                        mma16(c[mf][2 * i],     a[mf], bq[i][0], bq[i][1]);
                        mma16(c[mf][2 * i + 1], a[mf], bq[i][2], bq[i][3]);
                    }
            }
        }
    }

    const float* bb = biasP.p[j] + nn;
#pragma unroll
    for (int mf = 0; mf < 4; mf++) {
        int r0 = m0 + wm * 64 + mf * 16 + g;
#pragma unroll
        for (int nf = 0; nf < 8; nf++) {
            int cl = wn * 64 + nf * 8 + 2 * t;
            float bv0 = bb[cl], bv1 = bb[cl + 1];
            float v00 = c[mf][nf][0] + bv0, v01 = c[mf][nf][1] + bv1;
            float v10 = c[mf][nf][2] + bv0, v11 = c[mf][nf][3] + bv1;
            if (VAR == 2) {
                float* C = (float*)Cout;
                *(float2*)(C + (size_t)r0 * ldc + n0 + cl) = make_float2(v00, v01);
                *(float2*)(C + (size_t)(r0 + 8) * ldc + n0 + cl) = make_float2(v10, v11);
            } else {
                uint32_t* C = (uint32_t*)Cout;
                int lp = ldc >> 1;
                C[(size_t)r0 * lp + ((n0 + cl) >> 1)] = f2h2(v00, v01);
                C[(size_t)(r0 + 8) * lp + ((n0 + cl) >> 1)] = f2h2(v10, v11);
            }
        }
    }
}

// ---------------------------------------------------------------------------
// fp16 flash attention, 16 q-rows/warp, 128 q-rows/CTA, 2 CTAs/SM.
// P stays in registers (C-frag of S == A-frag of PV); one barrier per tile.
// ---------------------------------------------------------------------------
#define KWu 36
#define KSTGu (64 * KWu)
#define ATT_SMEM (4 * KSTGu * 4)   // 36864 B (K + V double-buffered)

__global__ __launch_bounds__(256, 2)
void flash_h(const __half* __restrict__ QKV, __half* __restrict__ OB)
{
    extern __shared__ uint32_t smu[];
    const uint32_t sbase = cvta_smem(smu);
    const uint32_t sK = sbase;
    const uint32_t sV = sbase + (uint32_t)(2 * KSTGu) * 4u;

    const int tid = threadIdx.x;
    const int w = tid >> 5, lane = tid & 31;
    const int g = lane >> 2, t = lane & 3;
    const int sel = lane >> 3, r8 = lane & 7;
    const int b = blockIdx.y >> 4, h = blockIdx.y & 15, z = blockIdx.z;
    const int q0 = blockIdx.x * 128;
    const size_t ld = 6144;

    const size_t base = (size_t)b * Ssz * ld + (size_t)z * 3072 + h * 64;
    const __half* Kg = QKV + base + 1024;
    const __half* Vg = QKV + base + 2048;

    // Q scale = log2(e)/8 : softmax runs in exp2 domain
    const __half2 scq = __float2half2_rn(0.18033688f);
    uint32_t qf[4][4];
#pragma unroll
    for (int q = 0; q < 4; q++) {
        int row = q0 + w * 16 + g + ((q & 1) ? 8 : 0);
        const __half2* Q2 = (const __half2*)QKV + ((base + (size_t)row * ld) >> 1);
#pragma unroll
        for (int kf = 0; kf < 4; kf++) {
            __half2 v = __hmul2(Q2[kf * 8 + t + ((q >> 1) ? 4 : 0)], scq);
            qf[kf][q] = *(uint32_t*)&v;
        }
    }

    float o[8][4] = {};
    float m0f = -1e30f, m1f = -1e30f, l0 = 0.f, l1 = 0.f;

    auto loadKV = [&](int buf, int tile) {
#pragma unroll
        for (int i = 0; i < 2; i++) {
            int idx = tid + i * 256;
            int row = idx >> 3, ch = idx & 7;
            size_t off = (size_t)(tile * 64 + row) * ld + ch * 8;
            cp16(sK + (uint32_t)(buf * KSTGu + row * KWu + ch * 4) * 4u, Kg + off);
            cp16(sV + (uint32_t)(buf * KSTGu + row * KWu + ch * 4) * 4u, Vg + off);
        }
        cp_commit();
    };

    const int NT = Ssz / 64;
    loadKV(0, 0);

    const int rowB = (sel >= 2) ? 8 : 0, colB = (sel & 1) ? 4 : 0;
    const int rowA = (sel & 1) ? 8 : 0, colA = (sel >= 2) ? 4 : 0;

    for (int tile = 0; tile < NT; tile++) {
        const int buf = tile & 1;
        // single barrier: publishes this tile's cp.async data AND guarantees
        // all warps finished reading the buffer the next prefetch overwrites
        cp_wait<0>();
        __syncthreads();
        if (tile + 1 < NT) loadKV(buf ^ 1, tile + 1);

        const uint32_t sKb = sK + (uint32_t)(buf * KSTGu) * 4u;
        const uint32_t sVb = sV + (uint32_t)(buf * KSTGu) * 4u;

        // S = Q K^T (16 x 64 per warp)
        float s[8][4] = {};
#pragma unroll
        for (int kf = 0; kf < 4; kf++) {
#pragma unroll
            for (int np = 0; np < 4; np++) {
                uint32_t kb[4];
                ldm_x4(kb, sKb + (uint32_t)((np * 16 + rowB + r8) * KWu + kf * 8 + colB) * 4u);
                mma16(s[2 * np],     qf[kf], kb[0], kb[1]);
                mma16(s[2 * np + 1], qf[kf], kb[2], kb[3]);
            }
        }

        // online softmax (exp2 domain); P packed directly into PV A-fragments
        float tmax0 = -1e30f, tmax1 = -1e30f;
#pragma unroll
        for (int nf = 0; nf < 8; nf++) {
            tmax0 = fmaxf(tmax0, fmaxf(s[nf][0], s[nf][1]));
            tmax1 = fmaxf(tmax1, fmaxf(s[nf][2], s[nf][3]));
        }
        tmax0 = fmaxf(tmax0, __shfl_xor_sync(0xffffffffu, tmax0, 1));
        tmax0 = fmaxf(tmax0, __shfl_xor_sync(0xffffffffu, tmax0, 2));
        tmax1 = fmaxf(tmax1, __shfl_xor_sync(0xffffffffu, tmax1, 1));
        tmax1 = fmaxf(tmax1, __shfl_xor_sync(0xffffffffu, tmax1, 2));

        float mn0 = fmaxf(m0f, tmax0), mn1 = fmaxf(m1f, tmax1);
        float al0 = ex2f(m0f - mn0), al1 = ex2f(m1f - mn1);

        uint32_t pa[4][4];
        float rs0 = 0.f, rs1 = 0.f;
#pragma unroll
        for (int nf = 0; nf < 8; nf++) {
            float p0 = ex2f(s[nf][0] - mn0);
            float p1 = ex2f(s[nf][1] - mn0);
            float p2 = ex2f(s[nf][2] - mn1);
            float p3 = ex2f(s[nf][3] - mn1);
            rs0 += p0 + p1; rs1 += p2 + p3;
            // C-frag (rows g,g+8 / cols 2t,2t+1 of n-tile nf) == A-frag slots:
            // even nf -> a[0],a[1] (k=2t,2t+1); odd nf -> a[2],a[3] (k=8+2t,..)
            pa[nf >> 1][(nf & 1) * 2 + 0] = f2h2(p0, p1);
            pa[nf >> 1][(nf & 1) * 2 + 1] = f2h2(p2, p3);
        }
        rs0 += __shfl_xor_sync(0xffffffffu, rs0, 1);
        rs0 += __shfl_xor_sync(0xffffffffu, rs0, 2);
        rs1 += __shfl_xor_sync(0xffffffffu, rs1, 1);
        rs1 += __shfl_xor_sync(0xffffffffu, rs1, 2);
        l0 = l0 * al0 + rs0;
        l1 = l1 * al1 + rs1;
        m0f = mn0; m1f = mn1;
#pragma unroll
        for (int nf = 0; nf < 8; nf++) {
            o[nf][0] *= al0; o[nf][1] *= al0;
            o[nf][2] *= al1; o[nf][3] *= al1;
        }

        // O += P V (P from registers, V via ldmatrix.trans)
#pragma unroll
        for (int kf = 0; kf < 4; kf++) {
#pragma unroll
            for (int np = 0; np < 4; np++) {
                uint32_t vb[4];
                ldm_x4t(vb, sVb + (uint32_t)((kf * 16 + rowA + r8) * KWu + np * 8 + colA) * 4u);
                mma16(o[2 * np],     pa[kf], vb[0], vb[1]);
                mma16(o[2 * np + 1], pa[kf], vb[2], vb[3]);
            }
        }
    }

    uint32_t* O2 = (uint32_t*)OB;
    float inv0 = 1.f / l0, inv1 = 1.f / l1;
    int row = q0 + w * 16 + g;
    size_t rb0 = (size_t)(b * Ssz + row) * 1024 + z * 512 + h * 32;
    size_t rb1 = rb0 + 8 * 1024;
#pragma unroll
    for (int nf = 0; nf < 8; nf++) {
        O2[rb0 + nf * 4 + t] = f2h2(o[nf][0] * inv0, o[nf][1] * inv0);
        O2[rb1 + nf * 4 + t] = f2h2(o[nf][2] * inv1, o[nf][3] * inv1);
    }
}

// ---------------------------------------------------------------------------
extern "C" void kernel_launch(void* const* d_in, const int* in_sizes, int n_in,
                              void* d_out, int out_size)
{
    const float*    x            = (const float*)d_in[0];
    const unsigned* layer_idx    = (const unsigned*)d_in[1];
    const float*    lambda_param = (const float*)d_in[2];

    const float *Wq1, *bq1, *Wk1, *bk1, *Wv1, *bv1, *Wo1, *bo1;
    const float *Wq2, *bq2, *Wk2, *bk2, *Wv2, *bv2, *Wo2, *bo2;

    bool sig_order = (in_sizes[4] < 100000);
    if (!sig_order) {
        Wq1 = (const float*)d_in[3];  Wk1 = (const float*)d_in[4];
        Wv1 = (const float*)d_in[5];  Wo1 = (const float*)d_in[6];
        bq1 = (const float*)d_in[7];  bk1 = (const float*)d_in[8];
        bv1 = (const float*)d_in[9];  bo1 = (const float*)d_in[10];
        Wq2 = (const float*)d_in[11]; Wk2 = (const float*)d_in[12];
        Wv2 = (const float*)d_in[13]; Wo2 = (const float*)d_in[14];
        bq2 = (const float*)d_in[15]; bk2 = (const float*)d_in[16];
        bv2 = (const float*)d_in[17]; bo2 = (const float*)d_in[18];
    } else {
        Wq1 = (const float*)d_in[3];  bq1 = (const float*)d_in[4];
        Wk1 = (const float*)d_in[5];  bk1 = (const float*)d_in[6];
        Wv1 = (const float*)d_in[7];  bv1 = (const float*)d_in[8];
        Wo1 = (const float*)d_in[9];  bo1 = (const float*)d_in[10];
        Wq2 = (const float*)d_in[11]; bq2 = (const float*)d_in[12];
        Wk2 = (const float*)d_in[13]; bk2 = (const float*)d_in[14];
        Wv2 = (const float*)d_in[15]; bv2 = (const float*)d_in[16];
        Wo2 = (const float*)d_in[17]; bo2 = (const float*)d_in[18];
    }
    const float* Wp = (const float*)d_in[19];
    const float* bp = (const float*)d_in[20];

    unsigned char* sc = nullptr;
    cudaGetSymbolAddress((void**)&sc, g_scratch);
    __half* XH  = (__half*)(sc + OFF_XH);
    __half* WT  = (__half*)(sc + OFF_WT);
    __half* QKV = (__half*)(sc + OFF_QKV);
    __half* OB  = (__half*)(sc + OFF_OB);
    __half* TB  = (__half*)(sc + OFF_TB);

    const int SMEM01 = 3 * (A_U + B_U) * 4;       // 92160
    const int SMEM2  = 3 * (2 * A_U + B_U) * 4;   // 122880

    cudaFuncSetAttribute(gemm_h<0>, cudaFuncAttributeMaxDynamicSharedMemorySize, SMEM01);
    cudaFuncSetAttribute(gemm_h<1>, cudaFuncAttributeMaxDynamicSharedMemorySize, SMEM01);
    cudaFuncSetAttribute(gemm_h<2>, cudaFuncAttributeMaxDynamicSharedMemorySize, SMEM2);
    cudaFuncSetAttribute(flash_h,   cudaFuncAttributeMaxDynamicSharedMemorySize, ATT_SMEM);

    conv_x<<<512, 256>>>((const float4*)x, (uint4*)XH);
    PtrsW srcW = {{ Wq1, Wk1, Wv1, Wq2, Wk2, Wv2, Wo1, Wo2, Wp }};
    trans_w<<<dim3(32, 32, 9), dim3(32, 8)>>>(srcW, (uint32_t*)WT);

    HPtrs6 wqkv = {{ WT + 0ull * 1048576, WT + 1ull * 1048576, WT + 2ull * 1048576,
                     WT + 3ull * 1048576, WT + 4ull * 1048576, WT + 5ull * 1048576 }};
    PtrsB bqkv = {{ bq1, bk1, bv1, bq2, bk2, bv2 }};
    gemm_h<0><<<dim3(24, 32), 256, SMEM01>>>(XH, wqkv, bqkv, QKV, 6144, 1024, 6144,
                                             nullptr, nullptr);

    flash_h<<<dim3(Ssz / 128, Bsz * Hsz, 2), 256, ATT_SMEM>>>(QKV, OB);

    HPtrs6 wwo = {{ WT + 6ull * 1048576, WT + 7ull * 1048576, nullptr, nullptr, nullptr, nullptr }};
    PtrsB bwo = {{ bo1, bo2, nullptr, nullptr, nullptr, nullptr }};
    gemm_h<1><<<dim3(8, 32), 256, SMEM01>>>(OB, wwo, bwo, TB, 2048, 2048, 2048,
                                            nullptr, nullptr);

    HPtrs6 wp  = {{ WT + 8ull * 1048576, nullptr, nullptr, nullptr, nullptr, nullptr }};
    PtrsB bpp = {{ bp, nullptr, nullptr, nullptr, nullptr, nullptr }};
    gemm_h<2><<<dim3(4, 32), 256, SMEM2>>>(TB, wp, bpp, d_out, 1024, 2048, 1024,
                                           lambda_param, layer_idx);
}

// round 10
// speedup vs baseline: 1.9873x; 1.1154x over previous
#include <cuda_runtime.h>
#include <cuda_fp16.h>
#include <math.h>
#include <stdint.h>

#define Bsz 2
#define Ssz 2048
#define Hsz 16
#define Msz 4096

// fp16 scratch: XH 8MB | WT 18MB | QKV 48MB | OB 16MB | TB 16MB
#define OFF_XH  0ull
#define OFF_WT  8388608ull
#define OFF_QKV 27262976ull
#define OFF_OB  77594624ull
#define OFF_TB  94371840ull
__device__ __align__(1024) unsigned char g_scratch[111149056ull];

// ---------------------------------------------------------------------------
// helpers
// ---------------------------------------------------------------------------
__device__ __forceinline__ uint32_t cvta_smem(const void* p) {
    uint32_t a;
    asm("{ .reg .u64 t; cvta.to.shared.u64 t, %1; cvt.u32.u64 %0, t; }"
        : "=r"(a) : "l"(p));
    return a;
}
__device__ __forceinline__ void cp16(uint32_t dst, const void* src) {
    asm volatile("cp.async.cg.shared.global [%0], [%1], 16;" :: "r"(dst), "l"(src));
}
__device__ __forceinline__ void cp_commit() { asm volatile("cp.async.commit_group;"); }
template <int N>
__device__ __forceinline__ void cp_wait() { asm volatile("cp.async.wait_group %0;" :: "n"(N)); }

__device__ __forceinline__ uint32_t f2h2(float lo, float hi) {
    uint32_t r;
    asm("cvt.rn.f16x2.f32 %0, %2, %1;" : "=r"(r) : "f"(lo), "f"(hi));
    return r;
}
__device__ __forceinline__ float2 h2f2(uint32_t u) {
    __half2 h = *reinterpret_cast<__half2*>(&u);
    return __half22float2(h);
}
__device__ __forceinline__ float ex2f(float x) {
    float r;
    asm("ex2.approx.f32 %0, %1;" : "=f"(r) : "f"(x));
    return r;
}
__device__ __forceinline__ uint32_t ex2h2(uint32_t x) {
    uint32_t r;
    asm("ex2.approx.f16x2 %0, %1;" : "=r"(r) : "r"(x));
    return r;
}

// mma m16n8k16 fp16 in, fp32 accum
__device__ __forceinline__ void mma16(float c[4], const uint32_t a[4],
                                      uint32_t b0, uint32_t b1) {
    asm volatile(
        "mma.sync.aligned.m16n8k16.row.col.f32.f16.f16.f32 "
        "{%0,%1,%2,%3}, {%4,%5,%6,%7}, {%8,%9}, {%0,%1,%2,%3};"
        : "+f"(c[0]), "+f"(c[1]), "+f"(c[2]), "+f"(c[3])
        : "r"(a[0]), "r"(a[1]), "r"(a[2]), "r"(a[3]), "r"(b0), "r"(b1));
}
__device__ __forceinline__ void ldm_x4(uint32_t r[4], uint32_t addr) {
    asm volatile("ldmatrix.sync.aligned.m8n8.x4.shared.b16 {%0,%1,%2,%3}, [%4];"
        : "=r"(r[0]), "=r"(r[1]), "=r"(r[2]), "=r"(r[3]) : "r"(addr));
}
__device__ __forceinline__ void ldm_x4t(uint32_t r[4], uint32_t addr) {
    asm volatile("ldmatrix.sync.aligned.m8n8.x4.trans.shared.b16 {%0,%1,%2,%3}, [%4];"
        : "=r"(r[0]), "=r"(r[1]), "=r"(r[2]), "=r"(r[3]) : "r"(addr));
}

struct PtrsW { const float* p[9]; };
struct PtrsB { const float* p[6]; };
struct HPtrs6 { const __half* p[6]; };

// ---------------------------------------------------------------------------
// prep 1: x fp32 -> fp16
// ---------------------------------------------------------------------------
__global__ void conv_x(const float4* __restrict__ in, uint4* __restrict__ out)
{
    const int n8 = Msz * 1024 / 8;
    int i = blockIdx.x * blockDim.x + threadIdx.x;
    int st = gridDim.x * blockDim.x;
    for (; i < n8; i += st) {
        float4 v0 = in[2 * i], v1 = in[2 * i + 1];
        uint4 o;
        o.x = f2h2(v0.x, v0.y); o.y = f2h2(v0.z, v0.w);
        o.z = f2h2(v1.x, v1.y); o.w = f2h2(v1.z, v1.w);
        out[i] = o;
    }
}

// ---------------------------------------------------------------------------
// prep 2: transpose+convert 9 weights [1024 k][1024 n] f32 -> [n][k] fp16
// ---------------------------------------------------------------------------
__global__ __launch_bounds__(256)
void trans_w(PtrsW src, uint32_t* __restrict__ dst)
{
    __shared__ float tsm[32][33];
    const int z = blockIdx.z;
    const float* W = src.p[z];
    uint32_t* out = dst + (size_t)z * (1024 * 512);
    const int bx = blockIdx.x * 32, by = blockIdx.y * 32;
    const int x = threadIdx.x, y = threadIdx.y;
    for (int i = y; i < 32; i += 8)
        tsm[i][x] = W[(size_t)(by + i) * 1024 + bx + x];
    __syncthreads();
    int tid = y * 32 + x;
#pragma unroll
    for (int s = 0; s < 2; s++) {
        int idx = tid + s * 256;
        int row = idx >> 4, p = idx & 15;
        out[(size_t)(bx + row) * 512 + (by >> 1) + p] =
            f2h2(tsm[2 * p][row], tsm[2 * p + 1][row]);
    }
}

// ---------------------------------------------------------------------------
// fp16 GEMM, CTA 128x128, BK=32, 8 warps (warp tile 32x64), 3-stage cp.async,
// 2 CTAs/SM. VAR 0/1: ldmatrix fragment loads. VAR 2: scalar + fused diff.
// ---------------------------------------------------------------------------
#define AW 20
#define BW 20
#define A_U (128 * AW)   // 2560 u32
#define B_U (128 * BW)   // 2560 u32

template <int VAR>
__global__ __launch_bounds__(256, 2)
void gemm_h(const __half* __restrict__ A, HPtrs6 Bp, PtrsB biasP,
            void* __restrict__ Cout, int N, int lda, int ldc,
            const float* __restrict__ lambda_param,
            const unsigned* __restrict__ layer_idx_bits)
{
    constexpr int A_ST = (VAR == 2) ? 2 * A_U : A_U;
    constexpr int STG = A_ST + B_U;
    extern __shared__ uint32_t smu[];
    const uint32_t sbase = cvta_smem(smu);

    const int tid = threadIdx.x;
    const int lane = tid & 31;
    const int g = lane >> 2, t = lane & 3;
    const int lrow = lane & 7, lsel = lane >> 3;
    const int wid = tid >> 5;
    const int wm = wid >> 1, wn = wid & 1;       // 4 x 2 warp grid
    const int m0 = blockIdx.y * 128, n0 = blockIdx.x * 128;
    const int j = n0 >> 10, nn = n0 & 1023;
    const int aoffr = (VAR == 1) ? (j << 10) : 0;

    float lam = 0.f;
    if (VAR == 2) {
        unsigned bits = *layer_idx_bits;
        float lf = (bits < 10000u) ? (float)bits : __uint_as_float(bits);
        float e = __expf(-0.3f * fmaxf(lf - 1.0f, 0.0f));
        lam = fminf(fmaxf((0.8f - 0.6f * e) * lambda_param[0], 0.1f), 0.9f);
    }

    const __half* Bj = Bp.p[j];
    float c[2][8][4] = {};

    const uint32_t aoff = (uint32_t)((wm * 32 + ((lsel & 1) ? 8 : 0) + lrow) * AW
                                     + ((lsel >> 1) ? 4 : 0)) * 4u;
    const uint32_t boff = (uint32_t)((wn * 64 + ((lsel >> 1) ? 8 : 0) + lrow) * BW
                                     + ((lsel & 1) ? 4 : 0)) * 4u;

    auto loadTile = [&](int stg, int kt) {
        uint32_t sa = sbase + (uint32_t)(stg * STG) * 4u;
        uint32_t sb = sa + (uint32_t)A_ST * 4u;
#pragma unroll
        for (int i = 0; i < 2; i++) {
            int idx = tid + i * 256;
            int row = idx >> 2, ch = idx & 3;
            const __half* src = A + (size_t)(m0 + row) * lda + aoffr + kt * 32 + ch * 8;
            cp16(sa + (uint32_t)(row * AW + ch * 4) * 4u, src);
            if (VAR == 2)
                cp16(sa + (uint32_t)(A_U + row * AW + ch * 4) * 4u, src + 1024);
        }
#pragma unroll
        for (int i = 0; i < 2; i++) {
            int idx = tid + i * 256;
            int row = idx >> 2, ch = idx & 3;
            cp16(sb + (uint32_t)(row * BW + ch * 4) * 4u,
                 Bj + (size_t)(nn + row) * 1024 + kt * 32 + ch * 8);
        }
        cp_commit();
    };

    const int T = 32;
    loadTile(0, 0); loadTile(1, 1);

    for (int kt = 0; kt < T; kt++) {
        const int stg = kt % 3;
        if (kt < T - 1) cp_wait<1>(); else cp_wait<0>();
        __syncthreads();
        if (kt + 2 < T) loadTile((kt + 2) % 3, kt + 2);

        if (VAR == 2) {
            const uint32_t* Au = smu + stg * STG;
            const uint32_t* Bu = Au + A_ST;
#pragma unroll
            for (int kf = 0; kf < 2; kf++) {
                uint32_t a[2][4];
#pragma unroll
                for (int mf = 0; mf < 2; mf++) {
                    int rb = wm * 32 + mf * 16;
#pragma unroll
                    for (int q = 0; q < 4; q++) {
                        int r = rb + g + ((q & 1) ? 8 : 0);
                        int kp = kf * 8 + t + ((q >> 1) ? 4 : 0);
                        float2 fu = h2f2(Au[r * AW + kp]);
                        float2 fv = h2f2(Au[A_U + r * AW + kp]);
                        a[mf][q] = f2h2(fmaf(-lam, fv.x, fu.x), fmaf(-lam, fv.y, fu.y));
                    }
                }
#pragma unroll
                for (int nf = 0; nf < 8; nf++) {
                    int n = wn * 64 + nf * 8 + g;
                    uint32_t b0 = Bu[n * BW + kf * 8 + t];
                    uint32_t b1 = Bu[n * BW + kf * 8 + 4 + t];
#pragma unroll
                    for (int mf = 0; mf < 2; mf++)
                        mma16(c[mf][nf], a[mf], b0, b1);
                }
            }
        } else {
            uint32_t aS = sbase + (uint32_t)(stg * STG) * 4u + aoff;
            uint32_t bS = sbase + (uint32_t)(stg * STG + A_ST) * 4u + boff;
#pragma unroll
            for (int kf = 0; kf < 2; kf++) {
                uint32_t a[2][4], bq[4][4];
#pragma unroll
                for (int mf = 0; mf < 2; mf++)
                    ldm_x4(a[mf], aS + (uint32_t)(mf * 16 * AW) * 4u + kf * 32u);
#pragma unroll
                for (int i = 0; i < 4; i++)
                    ldm_x4(bq[i], bS + (uint32_t)(i * 16 * BW) * 4u + kf * 32u);
#pragma unroll
                for (int i = 0; i < 4; i++)
#pragma unroll
                    for (int mf = 0; mf < 2; mf++) {
                        mma16(c[mf][2 * i],     a[mf], bq[i][0], bq[i][1]);
                        mma16(c[mf][2 * i + 1], a[mf], bq[i][2], bq[i][3]);
                    }
            }
        }
    }

    const float* bb = biasP.p[j] + nn;
#pragma unroll
    for (int mf = 0; mf < 2; mf++) {
        int r0 = m0 + wm * 32 + mf * 16 + g;
#pragma unroll
        for (int nf = 0; nf < 8; nf++) {
            int cl = wn * 64 + nf * 8 + 2 * t;
            float bv0 = bb[cl], bv1 = bb[cl + 1];
            float v00 = c[mf][nf][0] + bv0, v01 = c[mf][nf][1] + bv1;
            float v10 = c[mf][nf][2] + bv0, v11 = c[mf][nf][3] + bv1;
            if (VAR == 2) {
                float* C = (float*)Cout;
                *(float2*)(C + (size_t)r0 * ldc + n0 + cl) = make_float2(v00, v01);
                *(float2*)(C + (size_t)(r0 + 8) * ldc + n0 + cl) = make_float2(v10, v11);
            } else {
                uint32_t* C = (uint32_t*)Cout;
                int lp = ldc >> 1;
                C[(size_t)r0 * lp + ((n0 + cl) >> 1)] = f2h2(v00, v01);
                C[(size_t)(r0 + 8) * lp + ((n0 + cl) >> 1)] = f2h2(v10, v11);
            }
        }
    }
}

// ---------------------------------------------------------------------------
// fp16 flash attention, 16 q-rows/warp, 128 q-rows/CTA, 2 CTAs/SM.
// P in registers; exp via ex2.approx.f16x2; row-sums l via ones-MMA;
// rescale skipped when running max is stable.
// ---------------------------------------------------------------------------
#define KWu 36
#define KSTGu (64 * KWu)
#define ATT_SMEM (4 * KSTGu * 4)   // 36864 B

__global__ __launch_bounds__(256, 2)
void flash_h(const __half* __restrict__ QKV, __half* __restrict__ OB)
{
    extern __shared__ uint32_t smu[];
    const uint32_t sbase = cvta_smem(smu);
    const uint32_t sK = sbase;
    const uint32_t sV = sbase + (uint32_t)(2 * KSTGu) * 4u;

    const int tid = threadIdx.x;
    const int w = tid >> 5, lane = tid & 31;
    const int g = lane >> 2, t = lane & 3;
    const int sel = lane >> 3, r8 = lane & 7;
    const int b = blockIdx.y >> 4, h = blockIdx.y & 15, z = blockIdx.z;
    const int q0 = blockIdx.x * 128;
    const size_t ld = 6144;

    const size_t base = (size_t)b * Ssz * ld + (size_t)z * 3072 + h * 64;
    const __half* Kg = QKV + base + 1024;
    const __half* Vg = QKV + base + 2048;

    // Q scale = log2(e)/8 : softmax runs in exp2 domain
    const __half2 scq = __float2half2_rn(0.18033688f);
    uint32_t qf[4][4];
#pragma unroll
    for (int q = 0; q < 4; q++) {
        int row = q0 + w * 16 + g + ((q & 1) ? 8 : 0);
        const __half2* Q2 = (const __half2*)QKV + ((base + (size_t)row * ld) >> 1);
#pragma unroll
        for (int kf = 0; kf < 4; kf++) {
            __half2 v = __hmul2(Q2[kf * 8 + t + ((q >> 1) ? 4 : 0)], scq);
            qf[kf][q] = *(uint32_t*)&v;
        }
    }

    float o[8][4] = {};
    float lc[4] = {};                       // l row-sums via ones-MMA
    float m0f = -1e30f, m1f = -1e30f;
    const uint32_t ONE2 = 0x3C003C00u;      // half2(1.0, 1.0)

    auto loadKV = [&](int buf, int tile) {
#pragma unroll
        for (int i = 0; i < 2; i++) {
            int idx = tid + i * 256;
            int row = idx >> 3, ch = idx & 7;
            size_t off = (size_t)(tile * 64 + row) * ld + ch * 8;
            cp16(sK + (uint32_t)(buf * KSTGu + row * KWu + ch * 4) * 4u, Kg + off);
            cp16(sV + (uint32_t)(buf * KSTGu + row * KWu + ch * 4) * 4u, Vg + off);
        }
        cp_commit();
    };

    const int NT = Ssz / 64;
    loadKV(0, 0);

    const int rowB = (sel >= 2) ? 8 : 0, colB = (sel & 1) ? 4 : 0;
    const int rowA = (sel & 1) ? 8 : 0, colA = (sel >= 2) ? 4 : 0;

    for (int tile = 0; tile < NT; tile++) {
        const int buf = tile & 1;
        cp_wait<0>();
        __syncthreads();
        if (tile + 1 < NT) loadKV(buf ^ 1, tile + 1);

        const uint32_t sKb = sK + (uint32_t)(buf * KSTGu) * 4u;
        const uint32_t sVb = sV + (uint32_t)(buf * KSTGu) * 4u;

        // S = Q K^T (16 x 64 per warp)
        float s[8][4] = {};
#pragma unroll
        for (int kf = 0; kf < 4; kf++) {
#pragma unroll
            for (int np = 0; np < 4; np++) {
                uint32_t kb[4];
                ldm_x4(kb, sKb + (uint32_t)((np * 16 + rowB + r8) * KWu + kf * 8 + colB) * 4u);
                mma16(s[2 * np],     qf[kf], kb[0], kb[1]);
                mma16(s[2 * np + 1], qf[kf], kb[2], kb[3]);
            }
        }

        // tile max (quad-shuffle reduce)
        float tmax0 = -1e30f, tmax1 = -1e30f;
#pragma unroll
        for (int nf = 0; nf < 8; nf++) {
            tmax0 = fmaxf(tmax0, fmaxf(s[nf][0], s[nf][1]));
            tmax1 = fmaxf(tmax1, fmaxf(s[nf][2], s[nf][3]));
        }
        tmax0 = fmaxf(tmax0, __shfl_xor_sync(0xffffffffu, tmax0, 1));
        tmax0 = fmaxf(tmax0, __shfl_xor_sync(0xffffffffu, tmax0, 2));
        tmax1 = fmaxf(tmax1, __shfl_xor_sync(0xffffffffu, tmax1, 1));
        tmax1 = fmaxf(tmax1, __shfl_xor_sync(0xffffffffu, tmax1, 2));

        float mn0 = fmaxf(m0f, tmax0), mn1 = fmaxf(m1f, tmax1);

        // P fragments: pack (s - m) to half2, exp2 in fp16 domain
        uint32_t pa[4][4];
#pragma unroll
        for (int nf = 0; nf < 8; nf++) {
            uint32_t p01 = ex2h2(f2h2(s[nf][0] - mn0, s[nf][1] - mn0));
            uint32_t p23 = ex2h2(f2h2(s[nf][2] - mn1, s[nf][3] - mn1));
            pa[nf >> 1][(nf & 1) * 2 + 0] = p01;
            pa[nf >> 1][(nf & 1) * 2 + 1] = p23;
        }

        // rescale o and l only when the running max moved (warp-uniform)
        bool moved = !__all_sync(0xffffffffu, (mn0 == m0f) & (mn1 == m1f));
        if (moved) {
            float al0 = ex2f(m0f - mn0), al1 = ex2f(m1f - mn1);
            lc[0] *= al0; lc[1] *= al0; lc[2] *= al1; lc[3] *= al1;
#pragma unroll
            for (int nf = 0; nf < 8; nf++) {
                o[nf][0] *= al0; o[nf][1] *= al0;
                o[nf][2] *= al1; o[nf][3] *= al1;
            }
        }
        m0f = mn0; m1f = mn1;

        // l += row-sums of P (ones-MMA; every thread's c0/c2 = its row sums)
#pragma unroll
        for (int kf = 0; kf < 4; kf++)
            mma16(lc, pa[kf], ONE2, ONE2);

        // O += P V (P from registers, V via ldmatrix.trans)
#pragma unroll
        for (int kf = 0; kf < 4; kf++) {
#pragma unroll
            for (int np = 0; np < 4; np++) {
                uint32_t vb[4];
                ldm_x4t(vb, sVb + (uint32_t)((kf * 16 + rowA + r8) * KWu + np * 8 + colA) * 4u);
                mma16(o[2 * np],     pa[kf], vb[0], vb[1]);
                mma16(o[2 * np + 1], pa[kf], vb[2], vb[3]);
            }
        }
    }

    uint32_t* O2 = (uint32_t*)OB;
    float inv0 = 1.f / lc[0], inv1 = 1.f / lc[2];
    int row = q0 + w * 16 + g;
    size_t rb0 = (size_t)(b * Ssz + row) * 1024 + z * 512 + h * 32;
    size_t rb1 = rb0 + 8 * 1024;
#pragma unroll
    for (int nf = 0; nf < 8; nf++) {
        O2[rb0 + nf * 4 + t] = f2h2(o[nf][0] * inv0, o[nf][1] * inv0);
        O2[rb1 + nf * 4 + t] = f2h2(o[nf][2] * inv1, o[nf][3] * inv1);
    }
}

// ---------------------------------------------------------------------------
extern "C" void kernel_launch(void* const* d_in, const int* in_sizes, int n_in,
                              void* d_out, int out_size)
{
    const float*    x            = (const float*)d_in[0];
    const unsigned* layer_idx    = (const unsigned*)d_in[1];
    const float*    lambda_param = (const float*)d_in[2];

    const float *Wq1, *bq1, *Wk1, *bk1, *Wv1, *bv1, *Wo1, *bo1;
    const float *Wq2, *bq2, *Wk2, *bk2, *Wv2, *bv2, *Wo2, *bo2;

    bool sig_order = (in_sizes[4] < 100000);
    if (!sig_order) {
        Wq1 = (const float*)d_in[3];  Wk1 = (const float*)d_in[4];
        Wv1 = (const float*)d_in[5];  Wo1 = (const float*)d_in[6];
        bq1 = (const float*)d_in[7];  bk1 = (const float*)d_in[8];
        bv1 = (const float*)d_in[9];  bo1 = (const float*)d_in[10];
        Wq2 = (const float*)d_in[11]; Wk2 = (const float*)d_in[12];
        Wv2 = (const float*)d_in[13]; Wo2 = (const float*)d_in[14];
        bq2 = (const float*)d_in[15]; bk2 = (const float*)d_in[16];
        bv2 = (const float*)d_in[17]; bo2 = (const float*)d_in[18];
    } else {
        Wq1 = (const float*)d_in[3];  bq1 = (const float*)d_in[4];
        Wk1 = (const float*)d_in[5];  bk1 = (const float*)d_in[6];
        Wv1 = (const float*)d_in[7];  bv1 = (const float*)d_in[8];
        Wo1 = (const float*)d_in[9];  bo1 = (const float*)d_in[10];
        Wq2 = (const float*)d_in[11]; bq2 = (const float*)d_in[12];
        Wk2 = (const float*)d_in[13]; bk2 = (const float*)d_in[14];
        Wv2 = (const float*)d_in[15]; bv2 = (const float*)d_in[16];
        Wo2 = (const float*)d_in[17]; bo2 = (const float*)d_in[18];
    }
    const float* Wp = (const float*)d_in[19];
    const float* bp = (const float*)d_in[20];

    unsigned char* sc = nullptr;
    cudaGetSymbolAddress((void**)&sc, g_scratch);
    __half* XH  = (__half*)(sc + OFF_XH);
    __half* WT  = (__half*)(sc + OFF_WT);
    __half* QKV = (__half*)(sc + OFF_QKV);
    __half* OB  = (__half*)(sc + OFF_OB);
    __half* TB  = (__half*)(sc + OFF_TB);

    const int SMEM01 = 3 * (A_U + B_U) * 4;       // 61440
    const int SMEM2  = 3 * (2 * A_U + B_U) * 4;   // 92160

    cudaFuncSetAttribute(gemm_h<0>, cudaFuncAttributeMaxDynamicSharedMemorySize, SMEM01);
    cudaFuncSetAttribute(gemm_h<1>, cudaFuncAttributeMaxDynamicSharedMemorySize, SMEM01);
    cudaFuncSetAttribute(gemm_h<2>, cudaFuncAttributeMaxDynamicSharedMemorySize, SMEM2);
    cudaFuncSetAttribute(flash_h,   cudaFuncAttributeMaxDynamicSharedMemorySize, ATT_SMEM);

    conv_x<<<512, 256>>>((const float4*)x, (uint4*)XH);
    PtrsW srcW = {{ Wq1, Wk1, Wv1, Wq2, Wk2, Wv2, Wo1, Wo2, Wp }};
    trans_w<<<dim3(32, 32, 9), dim3(32, 8)>>>(srcW, (uint32_t*)WT);

    HPtrs6 wqkv = {{ WT + 0ull * 1048576, WT + 1ull * 1048576, WT + 2ull * 1048576,
                     WT + 3ull * 1048576, WT + 4ull * 1048576, WT + 5ull * 1048576 }};
    PtrsB bqkv = {{ bq1, bk1, bv1, bq2, bk2, bv2 }};
    gemm_h<0><<<dim3(48, 32), 256, SMEM01>>>(XH, wqkv, bqkv, QKV, 6144, 1024, 6144,
                                             nullptr, nullptr);

    flash_h<<<dim3(Ssz / 128, Bsz * Hsz, 2), 256, ATT_SMEM>>>(QKV, OB);

    HPtrs6 wwo = {{ WT + 6ull * 1048576, WT + 7ull * 1048576, nullptr, nullptr, nullptr, nullptr }};
    PtrsB bwo = {{ bo1, bo2, nullptr, nullptr, nullptr, nullptr }};
    gemm_h<1><<<dim3(16, 32), 256, SMEM01>>>(OB, wwo, bwo, TB, 2048, 2048, 2048,
                                             nullptr, nullptr);

    HPtrs6 wp  = {{ WT + 8ull * 1048576, nullptr, nullptr, nullptr, nullptr, nullptr }};
    PtrsB bpp = {{ bp, nullptr, nullptr, nullptr, nullptr, nullptr }};
    gemm_h<2><<<dim3(8, 32), 256, SMEM2>>>(TB, wp, bpp, d_out, 1024, 2048, 1024,
                                           lambda_param, layer_idx);
}

// round 11
// speedup vs baseline: 2.0843x; 1.0488x over previous
#include <cuda_runtime.h>
#include <cuda_fp16.h>
#include <math.h>
#include <stdint.h>

#define Bsz 2
#define Ssz 2048
#define Hsz 16
#define Msz 4096

// fp16 scratch: XH 8MB | WT 18MB | QKV 48MB | OB 16MB | TB 16MB
#define OFF_XH  0ull
#define OFF_WT  8388608ull
#define OFF_QKV 27262976ull
#define OFF_OB  77594624ull
#define OFF_TB  94371840ull
__device__ __align__(1024) unsigned char g_scratch[111149056ull];

// ---------------------------------------------------------------------------
// helpers
// ---------------------------------------------------------------------------
__device__ __forceinline__ uint32_t cvta_smem(const void* p) {
    uint32_t a;
    asm("{ .reg .u64 t; cvta.to.shared.u64 t, %1; cvt.u32.u64 %0, t; }"
        : "=r"(a) : "l"(p));
    return a;
}
__device__ __forceinline__ void cp16(uint32_t dst, const void* src) {
    asm volatile("cp.async.cg.shared.global [%0], [%1], 16;" :: "r"(dst), "l"(src));
}
__device__ __forceinline__ void cp_commit() { asm volatile("cp.async.commit_group;"); }
template <int N>
__device__ __forceinline__ void cp_wait() { asm volatile("cp.async.wait_group %0;" :: "n"(N)); }

__device__ __forceinline__ uint32_t f2h2(float lo, float hi) {
    uint32_t r;
    asm("cvt.rn.f16x2.f32 %0, %2, %1;" : "=r"(r) : "f"(lo), "f"(hi));
    return r;
}
__device__ __forceinline__ float2 h2f2(uint32_t u) {
    __half2 h = *reinterpret_cast<__half2*>(&u);
    return __half22float2(h);
}
__device__ __forceinline__ float ex2f(float x) {
    float r;
    asm("ex2.approx.f32 %0, %1;" : "=f"(r) : "f"(x));
    return r;
}
__device__ __forceinline__ uint32_t ex2h2(uint32_t x) {
    uint32_t r;
    asm("ex2.approx.f16x2 %0, %1;" : "=r"(r) : "r"(x));
    return r;
}

// mma m16n8k16 fp16 in, fp32 accum
__device__ __forceinline__ void mma16(float c[4], const uint32_t a[4],
                                      uint32_t b0, uint32_t b1) {
    asm volatile(
        "mma.sync.aligned.m16n8k16.row.col.f32.f16.f16.f32 "
        "{%0,%1,%2,%3}, {%4,%5,%6,%7}, {%8,%9}, {%0,%1,%2,%3};"
        : "+f"(c[0]), "+f"(c[1]), "+f"(c[2]), "+f"(c[3])
        : "r"(a[0]), "r"(a[1]), "r"(a[2]), "r"(a[3]), "r"(b0), "r"(b1));
}
__device__ __forceinline__ void ldm_x4(uint32_t r[4], uint32_t addr) {
    asm volatile("ldmatrix.sync.aligned.m8n8.x4.shared.b16 {%0,%1,%2,%3}, [%4];"
        : "=r"(r[0]), "=r"(r[1]), "=r"(r[2]), "=r"(r[3]) : "r"(addr));
}
__device__ __forceinline__ void ldm_x4t(uint32_t r[4], uint32_t addr) {
    asm volatile("ldmatrix.sync.aligned.m8n8.x4.trans.shared.b16 {%0,%1,%2,%3}, [%4];"
        : "=r"(r[0]), "=r"(r[1]), "=r"(r[2]), "=r"(r[3]) : "r"(addr));
}

struct PtrsW { const float* p[9]; };
struct PtrsB { const float* p[6]; };
struct HPtrs6 { const __half* p[6]; };

// ---------------------------------------------------------------------------
// prep 1: x fp32 -> fp16
// ---------------------------------------------------------------------------
__global__ void conv_x(const float4* __restrict__ in, uint4* __restrict__ out)
{
    const int n8 = Msz * 1024 / 8;
    int i = blockIdx.x * blockDim.x + threadIdx.x;
    int st = gridDim.x * blockDim.x;
    for (; i < n8; i += st) {
        float4 v0 = in[2 * i], v1 = in[2 * i + 1];
        uint4 o;
        o.x = f2h2(v0.x, v0.y); o.y = f2h2(v0.z, v0.w);
        o.z = f2h2(v1.x, v1.y); o.w = f2h2(v1.z, v1.w);
        out[i] = o;
    }
}

// ---------------------------------------------------------------------------
// prep 2: transpose+convert 9 weights [1024 k][1024 n] f32 -> [n][k] fp16
// ---------------------------------------------------------------------------
__global__ __launch_bounds__(256)
void trans_w(PtrsW src, uint32_t* __restrict__ dst)
{
    __shared__ float tsm[32][33];
    const int z = blockIdx.z;
    const float* W = src.p[z];
    uint32_t* out = dst + (size_t)z * (1024 * 512);
    const int bx = blockIdx.x * 32, by = blockIdx.y * 32;
    const int x = threadIdx.x, y = threadIdx.y;
    for (int i = y; i < 32; i += 8)
        tsm[i][x] = W[(size_t)(by + i) * 1024 + bx + x];
    __syncthreads();
    int tid = y * 32 + x;
#pragma unroll
    for (int s = 0; s < 2; s++) {
        int idx = tid + s * 256;
        int row = idx >> 4, p = idx & 15;
        out[(size_t)(bx + row) * 512 + (by >> 1) + p] =
            f2h2(tsm[2 * p][row], tsm[2 * p + 1][row]);
    }
}

// ---------------------------------------------------------------------------
// fp16 GEMM, CTA 128x128, BK=32, 4 warps (warp tile 64x64), 3-stage cp.async,
// 128 threads, 2 CTAs/SM. VAR 0/1: ldmatrix. VAR 2: scalar + fused diff.
// ---------------------------------------------------------------------------
#define AW 20
#define BW 20
#define A_U (128 * AW)   // 2560 u32
#define B_U (128 * BW)   // 2560 u32

template <int VAR>
__global__ __launch_bounds__(128, 2)
void gemm_h(const __half* __restrict__ A, HPtrs6 Bp, PtrsB biasP,
            void* __restrict__ Cout, int N, int lda, int ldc,
            const float* __restrict__ lambda_param,
            const unsigned* __restrict__ layer_idx_bits)
{
    constexpr int A_ST = (VAR == 2) ? 2 * A_U : A_U;
    constexpr int STG = A_ST + B_U;
    extern __shared__ uint32_t smu[];
    const uint32_t sbase = cvta_smem(smu);

    const int tid = threadIdx.x;
    const int lane = tid & 31;
    const int g = lane >> 2, t = lane & 3;
    const int lrow = lane & 7, lsel = lane >> 3;
    const int wid = tid >> 5;
    const int wm = wid >> 1, wn = wid & 1;       // 2 x 2 warp grid, 64x64 tiles
    const int m0 = blockIdx.y * 128, n0 = blockIdx.x * 128;
    const int j = n0 >> 10, nn = n0 & 1023;
    const int aoffr = (VAR == 1) ? (j << 10) : 0;

    float lam = 0.f;
    if (VAR == 2) {
        unsigned bits = *layer_idx_bits;
        float lf = (bits < 10000u) ? (float)bits : __uint_as_float(bits);
        float e = __expf(-0.3f * fmaxf(lf - 1.0f, 0.0f));
        lam = fminf(fmaxf((0.8f - 0.6f * e) * lambda_param[0], 0.1f), 0.9f);
    }

    const __half* Bj = Bp.p[j];
    float c[4][8][4] = {};

    const uint32_t aoff = (uint32_t)((wm * 64 + ((lsel & 1) ? 8 : 0) + lrow) * AW
                                     + ((lsel >> 1) ? 4 : 0)) * 4u;
    const uint32_t boff = (uint32_t)((wn * 64 + ((lsel >> 1) ? 8 : 0) + lrow) * BW
                                     + ((lsel & 1) ? 4 : 0)) * 4u;

    auto loadTile = [&](int stg, int kt) {
        uint32_t sa = sbase + (uint32_t)(stg * STG) * 4u;
        uint32_t sb = sa + (uint32_t)A_ST * 4u;
#pragma unroll
        for (int i = 0; i < 4; i++) {
            int idx = tid + i * 128;
            int row = idx >> 2, ch = idx & 3;
            const __half* src = A + (size_t)(m0 + row) * lda + aoffr + kt * 32 + ch * 8;
            cp16(sa + (uint32_t)(row * AW + ch * 4) * 4u, src);
            if (VAR == 2)
                cp16(sa + (uint32_t)(A_U + row * AW + ch * 4) * 4u, src + 1024);
        }
#pragma unroll
        for (int i = 0; i < 4; i++) {
            int idx = tid + i * 128;
            int row = idx >> 2, ch = idx & 3;
            cp16(sb + (uint32_t)(row * BW + ch * 4) * 4u,
                 Bj + (size_t)(nn + row) * 1024 + kt * 32 + ch * 8);
        }
        cp_commit();
    };

    const int T = 32;
    loadTile(0, 0); loadTile(1, 1);

    for (int kt = 0; kt < T; kt++) {
        const int stg = kt % 3;
        if (kt < T - 1) cp_wait<1>(); else cp_wait<0>();
        __syncthreads();
        if (kt + 2 < T) loadTile((kt + 2) % 3, kt + 2);

        if (VAR == 2) {
            const uint32_t* Au = smu + stg * STG;
            const uint32_t* Bu = Au + A_ST;
#pragma unroll
            for (int kf = 0; kf < 2; kf++) {
                uint32_t a[4][4];
#pragma unroll
                for (int mf = 0; mf < 4; mf++) {
                    int rb = wm * 64 + mf * 16;
#pragma unroll
                    for (int q = 0; q < 4; q++) {
                        int r = rb + g + ((q & 1) ? 8 : 0);
                        int kp = kf * 8 + t + ((q >> 1) ? 4 : 0);
                        float2 fu = h2f2(Au[r * AW + kp]);
                        float2 fv = h2f2(Au[A_U + r * AW + kp]);
                        a[mf][q] = f2h2(fmaf(-lam, fv.x, fu.x), fmaf(-lam, fv.y, fu.y));
                    }
                }
#pragma unroll
                for (int nf = 0; nf < 8; nf++) {
                    int n = wn * 64 + nf * 8 + g;
                    uint32_t b0 = Bu[n * BW + kf * 8 + t];
                    uint32_t b1 = Bu[n * BW + kf * 8 + 4 + t];
#pragma unroll
                    for (int mf = 0; mf < 4; mf++)
                        mma16(c[mf][nf], a[mf], b0, b1);
                }
            }
        } else {
            uint32_t aS = sbase + (uint32_t)(stg * STG) * 4u + aoff;
            uint32_t bS = sbase + (uint32_t)(stg * STG + A_ST) * 4u + boff;
#pragma unroll
            for (int kf = 0; kf < 2; kf++) {
                uint32_t a[4][4], bq[4][4];
#pragma unroll
                for (int mf = 0; mf < 4; mf++)
                    ldm_x4(a[mf], aS + (uint32_t)(mf * 16 * AW) * 4u + kf * 32u);
#pragma unroll
                for (int i = 0; i < 4; i++)
                    ldm_x4(bq[i], bS + (uint32_t)(i * 16 * BW) * 4u + kf * 32u);
#pragma unroll
                for (int i = 0; i < 4; i++)
#pragma unroll
                    for (int mf = 0; mf < 4; mf++) {
                        mma16(c[mf][2 * i],     a[mf], bq[i][0], bq[i][1]);
                        mma16(c[mf][2 * i + 1], a[mf], bq[i][2], bq[i][3]);
                    }
            }
        }
    }

    const float* bb = biasP.p[j] + nn;
#pragma unroll
    for (int mf = 0; mf < 4; mf++) {
        int r0 = m0 + wm * 64 + mf * 16 + g;
#pragma unroll
        for (int nf = 0; nf < 8; nf++) {
            int cl = wn * 64 + nf * 8 + 2 * t;
            float bv0 = bb[cl], bv1 = bb[cl + 1];
            float v00 = c[mf][nf][0] + bv0, v01 = c[mf][nf][1] + bv1;
            float v10 = c[mf][nf][2] + bv0, v11 = c[mf][nf][3] + bv1;
            if (VAR == 2) {
                float* C = (float*)Cout;
                *(float2*)(C + (size_t)r0 * ldc + n0 + cl) = make_float2(v00, v01);
                *(float2*)(C + (size_t)(r0 + 8) * ldc + n0 + cl) = make_float2(v10, v11);
            } else {
                uint32_t* C = (uint32_t*)Cout;
                int lp = ldc >> 1;
                C[(size_t)r0 * lp + ((n0 + cl) >> 1)] = f2h2(v00, v01);
                C[(size_t)(r0 + 8) * lp + ((n0 + cl) >> 1)] = f2h2(v10, v11);
            }
        }
    }
}

// ---------------------------------------------------------------------------
// fp16 flash attention: 4 warps x 32 q-rows (128 threads), 128 q-rows/CTA,
// 2 CTAs/SM. P in registers; f16x2 exp; ones-MMA row sums; lazy rescale.
// KV ldmatrix amortized over 2 m-fragments (half the smem traffic of R10).
// ---------------------------------------------------------------------------
#define KWu 36
#define KSTGu (64 * KWu)
#define ATT_SMEM (4 * KSTGu * 4)   // 36864 B

__global__ __launch_bounds__(128, 2)
void flash_h(const __half* __restrict__ QKV, __half* __restrict__ OB)
{
    extern __shared__ uint32_t smu[];
    const uint32_t sbase = cvta_smem(smu);
    const uint32_t sK = sbase;
    const uint32_t sV = sbase + (uint32_t)(2 * KSTGu) * 4u;

    const int tid = threadIdx.x;
    const int w = tid >> 5, lane = tid & 31;
    const int g = lane >> 2, t = lane & 3;
    const int sel = lane >> 3, r8 = lane & 7;
    const int b = blockIdx.y >> 4, h = blockIdx.y & 15, z = blockIdx.z;
    const int q0 = blockIdx.x * 128;
    const size_t ld = 6144;

    const size_t base = (size_t)b * Ssz * ld + (size_t)z * 3072 + h * 64;
    const __half* Kg = QKV + base + 1024;
    const __half* Vg = QKV + base + 2048;

    // Q scale = log2(e)/8 : softmax runs in exp2 domain
    const __half2 scq = __float2half2_rn(0.18033688f);
    uint32_t qf[2][4][4];
#pragma unroll
    for (int mf = 0; mf < 2; mf++) {
#pragma unroll
        for (int q = 0; q < 4; q++) {
            int row = q0 + w * 32 + mf * 16 + g + ((q & 1) ? 8 : 0);
            const __half2* Q2 = (const __half2*)QKV + ((base + (size_t)row * ld) >> 1);
#pragma unroll
            for (int kf = 0; kf < 4; kf++) {
                __half2 v = __hmul2(Q2[kf * 8 + t + ((q >> 1) ? 4 : 0)], scq);
                qf[mf][kf][q] = *(uint32_t*)&v;
            }
        }
    }

    float o[2][8][4] = {};
    float lc[2][4] = {};
    float mm[2][2] = { {-1e30f, -1e30f}, {-1e30f, -1e30f} };
    const uint32_t ONE2 = 0x3C003C00u;

    auto loadKV = [&](int buf, int tile) {
#pragma unroll
        for (int i = 0; i < 4; i++) {
            int idx = tid + i * 128;
            int row = idx >> 3, ch = idx & 7;
            size_t off = (size_t)(tile * 64 + row) * ld + ch * 8;
            cp16(sK + (uint32_t)(buf * KSTGu + row * KWu + ch * 4) * 4u, Kg + off);
            cp16(sV + (uint32_t)(buf * KSTGu + row * KWu + ch * 4) * 4u, Vg + off);
        }
        cp_commit();
    };

    const int NT = Ssz / 64;
    loadKV(0, 0);

    const int rowB = (sel >= 2) ? 8 : 0, colB = (sel & 1) ? 4 : 0;
    const int rowA = (sel & 1) ? 8 : 0, colA = (sel >= 2) ? 4 : 0;

    for (int tile = 0; tile < NT; tile++) {
        const int buf = tile & 1;
        cp_wait<0>();
        __syncthreads();
        if (tile + 1 < NT) loadKV(buf ^ 1, tile + 1);

        const uint32_t sKb = sK + (uint32_t)(buf * KSTGu) * 4u;
        const uint32_t sVb = sV + (uint32_t)(buf * KSTGu) * 4u;

        // S = Q K^T (32 x 64 per warp; K frags shared across both m-frags)
        float s[2][8][4] = {};
#pragma unroll
        for (int kf = 0; kf < 4; kf++) {
#pragma unroll
            for (int np = 0; np < 4; np++) {
                uint32_t kb[4];
                ldm_x4(kb, sKb + (uint32_t)((np * 16 + rowB + r8) * KWu + kf * 8 + colB) * 4u);
                mma16(s[0][2 * np],     qf[0][kf], kb[0], kb[1]);
                mma16(s[0][2 * np + 1], qf[0][kf], kb[2], kb[3]);
                mma16(s[1][2 * np],     qf[1][kf], kb[0], kb[1]);
                mma16(s[1][2 * np + 1], qf[1][kf], kb[2], kb[3]);
            }
        }

        // online softmax per m-fragment; P packed directly into A-fragments
        uint32_t pa[2][4][4];
        bool any_moved = false;
#pragma unroll
        for (int mf = 0; mf < 2; mf++) {
            float tmax0 = -1e30f, tmax1 = -1e30f;
#pragma unroll
            for (int nf = 0; nf < 8; nf++) {
                tmax0 = fmaxf(tmax0, fmaxf(s[mf][nf][0], s[mf][nf][1]));
                tmax1 = fmaxf(tmax1, fmaxf(s[mf][nf][2], s[mf][nf][3]));
            }
            tmax0 = fmaxf(tmax0, __shfl_xor_sync(0xffffffffu, tmax0, 1));
            tmax0 = fmaxf(tmax0, __shfl_xor_sync(0xffffffffu, tmax0, 2));
            tmax1 = fmaxf(tmax1, __shfl_xor_sync(0xffffffffu, tmax1, 1));
            tmax1 = fmaxf(tmax1, __shfl_xor_sync(0xffffffffu, tmax1, 2));

            float mn0 = fmaxf(mm[mf][0], tmax0), mn1 = fmaxf(mm[mf][1], tmax1);

#pragma unroll
            for (int nf = 0; nf < 8; nf++) {
                uint32_t p01 = ex2h2(f2h2(s[mf][nf][0] - mn0, s[mf][nf][1] - mn0));
                uint32_t p23 = ex2h2(f2h2(s[mf][nf][2] - mn1, s[mf][nf][3] - mn1));
                pa[mf][nf >> 1][(nf & 1) * 2 + 0] = p01;
                pa[mf][nf >> 1][(nf & 1) * 2 + 1] = p23;
            }

            bool moved = !__all_sync(0xffffffffu, (mn0 == mm[mf][0]) & (mn1 == mm[mf][1]));
            if (moved) {
                float al0 = ex2f(mm[mf][0] - mn0), al1 = ex2f(mm[mf][1] - mn1);
                lc[mf][0] *= al0; lc[mf][2] *= al1;
#pragma unroll
                for (int nf = 0; nf < 8; nf++) {
                    o[mf][nf][0] *= al0; o[mf][nf][1] *= al0;
                    o[mf][nf][2] *= al1; o[mf][nf][3] *= al1;
                }
            }
            mm[mf][0] = mn0; mm[mf][1] = mn1;
        }
        (void)any_moved;

        // l += row-sums of P (ones-MMA)
#pragma unroll
        for (int kf = 0; kf < 4; kf++) {
            mma16(lc[0], pa[0][kf], ONE2, ONE2);
            mma16(lc[1], pa[1][kf], ONE2, ONE2);
        }

        // O += P V (V frags shared across both m-frags)
#pragma unroll
        for (int kf = 0; kf < 4; kf++) {
#pragma unroll
            for (int np = 0; np < 4; np++) {
                uint32_t vb[4];
                ldm_x4t(vb, sVb + (uint32_t)((kf * 16 + rowA + r8) * KWu + np * 8 + colA) * 4u);
                mma16(o[0][2 * np],     pa[0][kf], vb[0], vb[1]);
                mma16(o[0][2 * np + 1], pa[0][kf], vb[2], vb[3]);
                mma16(o[1][2 * np],     pa[1][kf], vb[0], vb[1]);
                mma16(o[1][2 * np + 1], pa[1][kf], vb[2], vb[3]);
            }
        }
    }

    uint32_t* O2 = (uint32_t*)OB;
#pragma unroll
    for (int mf = 0; mf < 2; mf++) {
        float inv0 = 1.f / lc[mf][0], inv1 = 1.f / lc[mf][2];
        int row = q0 + w * 32 + mf * 16 + g;
        size_t rb0 = (size_t)(b * Ssz + row) * 1024 + z * 512 + h * 32;
        size_t rb1 = rb0 + 8 * 1024;
#pragma unroll
        for (int nf = 0; nf < 8; nf++) {
            O2[rb0 + nf * 4 + t] = f2h2(o[mf][nf][0] * inv0, o[mf][nf][1] * inv0);
            O2[rb1 + nf * 4 + t] = f2h2(o[mf][nf][2] * inv1, o[mf][nf][3] * inv1);
        }
    }
}

// ---------------------------------------------------------------------------
extern "C" void kernel_launch(void* const* d_in, const int* in_sizes, int n_in,
                              void* d_out, int out_size)
{
    const float*    x            = (const float*)d_in[0];
    const unsigned* layer_idx    = (const unsigned*)d_in[1];
    const float*    lambda_param = (const float*)d_in[2];

    const float *Wq1, *bq1, *Wk1, *bk1, *Wv1, *bv1, *Wo1, *bo1;
    const float *Wq2, *bq2, *Wk2, *bk2, *Wv2, *bv2, *Wo2, *bo2;

    bool sig_order = (in_sizes[4] < 100000);
    if (!sig_order) {
        Wq1 = (const float*)d_in[3];  Wk1 = (const float*)d_in[4];
        Wv1 = (const float*)d_in[5];  Wo1 = (const float*)d_in[6];
        bq1 = (const float*)d_in[7];  bk1 = (const float*)d_in[8];
        bv1 = (const float*)d_in[9];  bo1 = (const float*)d_in[10];
        Wq2 = (const float*)d_in[11]; Wk2 = (const float*)d_in[12];
        Wv2 = (const float*)d_in[13]; Wo2 = (const float*)d_in[14];
        bq2 = (const float*)d_in[15]; bk2 = (const float*)d_in[16];
        bv2 = (const float*)d_in[17]; bo2 = (const float*)d_in[18];
    } else {
        Wq1 = (const float*)d_in[3];  bq1 = (const float*)d_in[4];
        Wk1 = (const float*)d_in[5];  bk1 = (const float*)d_in[6];
        Wv1 = (const float*)d_in[7];  bv1 = (const float*)d_in[8];
        Wo1 = (const float*)d_in[9];  bo1 = (const float*)d_in[10];
        Wq2 = (const float*)d_in[11]; bq2 = (const float*)d_in[12];
        Wk2 = (const float*)d_in[13]; bk2 = (const float*)d_in[14];
        Wv2 = (const float*)d_in[15]; bv2 = (const float*)d_in[16];
        Wo2 = (const float*)d_in[17]; bo2 = (const float*)d_in[18];
    }
    const float* Wp = (const float*)d_in[19];
    const float* bp = (const float*)d_in[20];

    unsigned char* sc = nullptr;
    cudaGetSymbolAddress((void**)&sc, g_scratch);
    __half* XH  = (__half*)(sc + OFF_XH);
    __half* WT  = (__half*)(sc + OFF_WT);
    __half* QKV = (__half*)(sc + OFF_QKV);
    __half* OB  = (__half*)(sc + OFF_OB);
    __half* TB  = (__half*)(sc + OFF_TB);

    const int SMEM01 = 3 * (A_U + B_U) * 4;       // 61440
    const int SMEM2  = 3 * (2 * A_U + B_U) * 4;   // 92160

    cudaFuncSetAttribute(gemm_h<0>, cudaFuncAttributeMaxDynamicSharedMemorySize, SMEM01);
    cudaFuncSetAttribute(gemm_h<1>, cudaFuncAttributeMaxDynamicSharedMemorySize, SMEM01);
    cudaFuncSetAttribute(gemm_h<2>, cudaFuncAttributeMaxDynamicSharedMemorySize, SMEM2);
    cudaFuncSetAttribute(flash_h,   cudaFuncAttributeMaxDynamicSharedMemorySize, ATT_SMEM);

    conv_x<<<512, 256>>>((const float4*)x, (uint4*)XH);
    PtrsW srcW = {{ Wq1, Wk1, Wv1, Wq2, Wk2, Wv2, Wo1, Wo2, Wp }};
    trans_w<<<dim3(32, 32, 9), dim3(32, 8)>>>(srcW, (uint32_t*)WT);

    HPtrs6 wqkv = {{ WT + 0ull * 1048576, WT + 1ull * 1048576, WT + 2ull * 1048576,
                     WT + 3ull * 1048576, WT + 4ull * 1048576, WT + 5ull * 1048576 }};
    PtrsB bqkv = {{ bq1, bk1, bv1, bq2, bk2, bv2 }};
    gemm_h<0><<<dim3(48, 32), 128, SMEM01>>>(XH, wqkv, bqkv, QKV, 6144, 1024, 6144,
                                             nullptr, nullptr);

    flash_h<<<dim3(Ssz / 128, Bsz * Hsz, 2), 128, ATT_SMEM>>>(QKV, OB);

    HPtrs6 wwo = {{ WT + 6ull * 1048576, WT + 7ull * 1048576, nullptr, nullptr, nullptr, nullptr }};
    PtrsB bwo = {{ bo1, bo2, nullptr, nullptr, nullptr, nullptr }};
    gemm_h<1><<<dim3(16, 32), 128, SMEM01>>>(OB, wwo, bwo, TB, 2048, 2048, 2048,
                                             nullptr, nullptr);

    HPtrs6 wp  = {{ WT + 8ull * 1048576, nullptr, nullptr, nullptr, nullptr, nullptr }};
    PtrsB bpp = {{ bp, nullptr, nullptr, nullptr, nullptr, nullptr }};
    gemm_h<2><<<dim3(8, 32), 128, SMEM2>>>(TB, wp, bpp, d_out, 1024, 2048, 1024,
                                           lambda_param, layer_idx);
}